// round 2
// baseline (speedup 1.0000x reference)
#include <cuda_runtime.h>
#include <math.h>

// ---------------------------------------------------------------------------
// SiglipAttention: B=8, N=1024, D=1152, H=16, Hd=72
// Outputs (concatenated in d_out): out [B,N,D] fp32, attn_probs [B,H,N,N] fp32
// ---------------------------------------------------------------------------

#define BD   8
#define SEQ  1024
#define DIM  1152
#define NH   16
#define HD   72
#define MTOT (BD * SEQ)                 // 8192
#define QKV_ELEMS (BD * NH * SEQ * HD)  // 9437184
#define OUT_ELEMS (BD * SEQ * DIM)      // 9437184
#define SCALE_F 0.117851130197757931f   // 72^-0.5

// Scratch (allocation-free rule: __device__ globals)
__device__ float g_q[QKV_ELEMS];    // [B,H,N,Hd]
__device__ float g_kT[QKV_ELEMS];   // [B,H,Hd,N]  (transposed for attention)
__device__ float g_v[QKV_ELEMS];    // [B,H,N,Hd]
__device__ float g_ctx[QKV_ELEMS];  // [B,H,N,Hd]

// ---------------------------------------------------------------------------
// Kernel 1: fused QKV projection.  y = x @ W^T + b  (NT SGEMM, both K-major)
// 128x128 block tile, BK=8, 256 threads, 8x8 microtile.
// blockIdx.z selects projection {q,k,v}; epilogue scatters to head layout.
// ---------------------------------------------------------------------------
__global__ __launch_bounds__(256) void qkv_kernel(
    const float* __restrict__ x,
    const float* __restrict__ qw, const float* __restrict__ qb,
    const float* __restrict__ kw, const float* __restrict__ kb,
    const float* __restrict__ vw, const float* __restrict__ vb)
{
    const int proj = blockIdx.z;
    const float* w    = (proj == 0) ? qw : (proj == 1) ? kw : vw;
    const float* bias = (proj == 0) ? qb : (proj == 1) ? kb : vb;

    __shared__ float As[8][128];
    __shared__ float Bs[8][128];

    const int tid = threadIdx.x;
    const int tm = tid >> 4;         // 0..15
    const int tn = tid & 15;         // 0..15
    const int m0 = blockIdx.y * 128;
    const int n0 = blockIdx.x * 128;
    const int lr = tid >> 1;         // 0..127
    const int lk = (tid & 1) * 4;    // 0 or 4

    float acc[8][8];
#pragma unroll
    for (int i = 0; i < 8; i++)
#pragma unroll
        for (int j = 0; j < 8; j++) acc[i][j] = 0.f;

    for (int k0 = 0; k0 < DIM; k0 += 8) {
        float4 a4 = *(const float4*)(x + (size_t)(m0 + lr) * DIM + k0 + lk);
        float4 b4 = *(const float4*)(w + (size_t)(n0 + lr) * DIM + k0 + lk);
        __syncthreads();
        As[lk + 0][lr] = a4.x; As[lk + 1][lr] = a4.y;
        As[lk + 2][lr] = a4.z; As[lk + 3][lr] = a4.w;
        Bs[lk + 0][lr] = b4.x; Bs[lk + 1][lr] = b4.y;
        Bs[lk + 2][lr] = b4.z; Bs[lk + 3][lr] = b4.w;
        __syncthreads();
#pragma unroll
        for (int kk = 0; kk < 8; kk++) {
            float a[8], b[8];
            float4 t0 = *(const float4*)&As[kk][tm * 8];
            float4 t1 = *(const float4*)&As[kk][tm * 8 + 4];
            a[0]=t0.x; a[1]=t0.y; a[2]=t0.z; a[3]=t0.w;
            a[4]=t1.x; a[5]=t1.y; a[6]=t1.z; a[7]=t1.w;
            float4 u0 = *(const float4*)&Bs[kk][tn * 8];
            float4 u1 = *(const float4*)&Bs[kk][tn * 8 + 4];
            b[0]=u0.x; b[1]=u0.y; b[2]=u0.z; b[3]=u0.w;
            b[4]=u1.x; b[5]=u1.y; b[6]=u1.z; b[7]=u1.w;
#pragma unroll
            for (int i = 0; i < 8; i++)
#pragma unroll
                for (int j = 0; j < 8; j++) acc[i][j] += a[i] * b[j];
        }
    }

#pragma unroll
    for (int i = 0; i < 8; i++) {
        const int m = m0 + tm * 8 + i;
        const int bb = m >> 10;
        const int n  = m & 1023;
#pragma unroll
        for (int j = 0; j < 8; j++) {
            const int o  = n0 + tn * 8 + j;
            const int h  = o / HD;
            const int hd = o % HD;
            const float y = acc[i][j] + bias[o];
            if (proj == 1) {
                g_kT[((size_t)(bb * NH + h) * HD + hd) * SEQ + n] = y;
            } else {
                float* dst = (proj == 0) ? g_q : g_v;
                dst[((size_t)(bb * NH + h) * SEQ + n) * HD + hd] = y;
            }
        }
    }
}

// ---------------------------------------------------------------------------
// Kernel 2: fused attention for one (b,h,32-query) block.
//   scores (q.k * scale) -> smem, warp softmax, write probs, PV -> g_ctx
// smem: sq 32x72 | skv 72x128 (K tile, reused as 128x72 V tile) | ss 32x1024
// ---------------------------------------------------------------------------
#define ATTN_SMEM_FLOATS (32 * HD + HD * 128 + 32 * SEQ)   // 44288
#define ATTN_SMEM_BYTES  (ATTN_SMEM_FLOATS * 4)            // 177152

__global__ __launch_bounds__(256) void attn_kernel(float* __restrict__ probs)
{
    extern __shared__ float smem[];
    float* sq  = smem;                 // [32][72], pre-scaled by SCALE
    float* skv = smem + 32 * HD;       // K tile [72][128] / V tile [128][72]
    float* ss  = skv + HD * 128;       // [32][1024]

    const int tid = threadIdx.x;
    const int q0  = blockIdx.x * 32;
    const int bh  = blockIdx.z * NH + blockIdx.y;

    const float* qg  = g_q  + ((size_t)bh * SEQ + q0) * HD;
    const float* kTg = g_kT + (size_t)bh * HD * SEQ;
    const float* vg  = g_v  + (size_t)bh * SEQ * HD;
    float*       pg  = probs + ((size_t)bh * SEQ + q0) * SEQ;

    for (int i = tid; i < 32 * HD; i += 256) sq[i] = qg[i] * SCALE_F;

    // ---- scores: 32 queries x 1024 keys, tiles of 128 keys ----
    const int tx = tid & 31;   // key group (4 keys)
    const int ty = tid >> 5;   // query group (4 queries)
    for (int kt = 0; kt < 8; kt++) {
        for (int i = tid; i < HD * 128; i += 256) {
            const int hd = i >> 7, n = i & 127;
            skv[i] = kTg[hd * SEQ + kt * 128 + n];
        }
        __syncthreads();

        float a00=0,a01=0,a02=0,a03=0, a10=0,a11=0,a12=0,a13=0;
        float a20=0,a21=0,a22=0,a23=0, a30=0,a31=0,a32=0,a33=0;
#pragma unroll 4
        for (int kk = 0; kk < HD; kk++) {
            const float4 kv = *(const float4*)(skv + kk * 128 + tx * 4);
            const float qv0 = sq[(ty * 4 + 0) * HD + kk];
            const float qv1 = sq[(ty * 4 + 1) * HD + kk];
            const float qv2 = sq[(ty * 4 + 2) * HD + kk];
            const float qv3 = sq[(ty * 4 + 3) * HD + kk];
            a00 += qv0*kv.x; a01 += qv0*kv.y; a02 += qv0*kv.z; a03 += qv0*kv.w;
            a10 += qv1*kv.x; a11 += qv1*kv.y; a12 += qv1*kv.z; a13 += qv1*kv.w;
            a20 += qv2*kv.x; a21 += qv2*kv.y; a22 += qv2*kv.z; a23 += qv2*kv.w;
            a30 += qv3*kv.x; a31 += qv3*kv.y; a32 += qv3*kv.z; a33 += qv3*kv.w;
        }
        float* s0 = ss + (ty * 4 + 0) * SEQ + kt * 128 + tx * 4;
        float* s1 = ss + (ty * 4 + 1) * SEQ + kt * 128 + tx * 4;
        float* s2 = ss + (ty * 4 + 2) * SEQ + kt * 128 + tx * 4;
        float* s3 = ss + (ty * 4 + 3) * SEQ + kt * 128 + tx * 4;
        s0[0]=a00; s0[1]=a01; s0[2]=a02; s0[3]=a03;
        s1[0]=a10; s1[1]=a11; s1[2]=a12; s1[3]=a13;
        s2[0]=a20; s2[1]=a21; s2[2]=a22; s2[3]=a23;
        s3[0]=a30; s3[1]=a31; s3[2]=a32; s3[3]=a33;
        __syncthreads();
    }

    // ---- softmax: 8 warps x 4 rows ----
    {
        const int w = tid >> 5, l = tid & 31;
        for (int r = 0; r < 4; r++) {
            float* row = ss + (w * 4 + r) * SEQ;
            float m = -1e30f;
            for (int c = l; c < SEQ; c += 32) m = fmaxf(m, row[c]);
#pragma unroll
            for (int o = 16; o; o >>= 1) m = fmaxf(m, __shfl_xor_sync(~0u, m, o));
            float s = 0.f;
            for (int c = l; c < SEQ; c += 32) {
                const float e = __expf(row[c] - m);
                row[c] = e;
                s += e;
            }
#pragma unroll
            for (int o = 16; o; o >>= 1) s += __shfl_xor_sync(~0u, s, o);
            const float inv = 1.f / s;
            for (int c = l; c < SEQ; c += 32) row[c] *= inv;
        }
    }
    __syncthreads();

    // ---- write probs (contiguous 32x1024 block) ----
    for (int i = tid; i < 32 * SEQ; i += 256) pg[i] = ss[i];

    // ---- PV: ctx[32x72] = probs[32x1024] @ v[1024x72] ----
    // threads 0..127: 16 query-pairs x 8 hd-groups(9 each)
    const int qp = tid >> 3;   // 0..15 (valid when tid<128)
    const int gg = tid & 7;    // 0..7
    float c0[9], c1[9];
#pragma unroll
    for (int j = 0; j < 9; j++) { c0[j] = 0.f; c1[j] = 0.f; }

    for (int kt = 0; kt < 8; kt++) {
        __syncthreads();
        for (int i = tid; i < 128 * HD; i += 256)
            skv[i] = vg[(size_t)kt * 128 * HD + i];
        __syncthreads();
        if (tid < 128) {
#pragma unroll 4
            for (int key = 0; key < 128; key++) {
                const float p0 = ss[(qp * 2 + 0) * SEQ + kt * 128 + key];
                const float p1 = ss[(qp * 2 + 1) * SEQ + kt * 128 + key];
                const float* vrow = skv + key * HD + gg * 9;
#pragma unroll
                for (int j = 0; j < 9; j++) {
                    const float vv = vrow[j];
                    c0[j] += p0 * vv;
                    c1[j] += p1 * vv;
                }
            }
        }
    }

    if (tid < 128) {
        float* d0 = g_ctx + ((size_t)bh * SEQ + q0 + qp * 2 + 0) * HD + gg * 9;
        float* d1 = g_ctx + ((size_t)bh * SEQ + q0 + qp * 2 + 1) * HD + gg * 9;
#pragma unroll
        for (int j = 0; j < 9; j++) { d0[j] = c0[j]; d1[j] = c1[j]; }
    }
}

// ---------------------------------------------------------------------------
// Kernel 3: O projection.  out = ctx @ o_w^T + o_b
// Same SGEMM; A loads gather from head layout [B,H,N,Hd].
// Note: k%72 is always a multiple of 4 and 4-runs never cross a head boundary.
// ---------------------------------------------------------------------------
__global__ __launch_bounds__(256) void oproj_kernel(
    const float* __restrict__ ow, const float* __restrict__ ob,
    float* __restrict__ out)
{
    __shared__ float As[8][128];
    __shared__ float Bs[8][128];

    const int tid = threadIdx.x;
    const int tm = tid >> 4, tn = tid & 15;
    const int m0 = blockIdx.y * 128;
    const int n0 = blockIdx.x * 128;
    const int lr = tid >> 1;
    const int lk = (tid & 1) * 4;

    float acc[8][8];
#pragma unroll
    for (int i = 0; i < 8; i++)
#pragma unroll
        for (int j = 0; j < 8; j++) acc[i][j] = 0.f;

    const int m  = m0 + lr;
    const int bb = m >> 10;
    const int n  = m & 1023;

    for (int k0 = 0; k0 < DIM; k0 += 8) {
        const int k  = k0 + lk;
        const int h  = k / HD;
        const int hd = k % HD;
        float4 a4 = *(const float4*)(g_ctx + ((size_t)(bb * NH + h) * SEQ + n) * HD + hd);
        float4 b4 = *(const float4*)(ow + (size_t)(n0 + lr) * DIM + k0 + lk);
        __syncthreads();
        As[lk + 0][lr] = a4.x; As[lk + 1][lr] = a4.y;
        As[lk + 2][lr] = a4.z; As[lk + 3][lr] = a4.w;
        Bs[lk + 0][lr] = b4.x; Bs[lk + 1][lr] = b4.y;
        Bs[lk + 2][lr] = b4.z; Bs[lk + 3][lr] = b4.w;
        __syncthreads();
#pragma unroll
        for (int kk = 0; kk < 8; kk++) {
            float a[8], b[8];
            float4 t0 = *(const float4*)&As[kk][tm * 8];
            float4 t1 = *(const float4*)&As[kk][tm * 8 + 4];
            a[0]=t0.x; a[1]=t0.y; a[2]=t0.z; a[3]=t0.w;
            a[4]=t1.x; a[5]=t1.y; a[6]=t1.z; a[7]=t1.w;
            float4 u0 = *(const float4*)&Bs[kk][tn * 8];
            float4 u1 = *(const float4*)&Bs[kk][tn * 8 + 4];
            b[0]=u0.x; b[1]=u0.y; b[2]=u0.z; b[3]=u0.w;
            b[4]=u1.x; b[5]=u1.y; b[6]=u1.z; b[7]=u1.w;
#pragma unroll
            for (int i = 0; i < 8; i++)
#pragma unroll
                for (int j = 0; j < 8; j++) acc[i][j] += a[i] * b[j];
        }
    }

#pragma unroll
    for (int i = 0; i < 8; i++) {
        const int mm = m0 + tm * 8 + i;
#pragma unroll
        for (int j = 0; j < 8; j++) {
            const int o = n0 + tn * 8 + j;
            out[(size_t)mm * DIM + o] = acc[i][j] + ob[o];
        }
    }
}

// ---------------------------------------------------------------------------
extern "C" void kernel_launch(void* const* d_in, const int* in_sizes, int n_in,
                              void* d_out, int out_size)
{
    const float* x  = (const float*)d_in[0];
    const float* qw = (const float*)d_in[1];
    const float* qb = (const float*)d_in[2];
    const float* kw = (const float*)d_in[3];
    const float* kb = (const float*)d_in[4];
    const float* vw = (const float*)d_in[5];
    const float* vb = (const float*)d_in[6];
    const float* ow = (const float*)d_in[7];
    const float* ob = (const float*)d_in[8];

    float* out   = (float*)d_out;            // [B,N,D]
    float* probs = out + OUT_ELEMS;          // [B,H,N,N]

    cudaFuncSetAttribute(attn_kernel,
                         cudaFuncAttributeMaxDynamicSharedMemorySize,
                         ATTN_SMEM_BYTES);

    dim3 gq(DIM / 128, MTOT / 128, 3);       // (9, 64, 3)
    qkv_kernel<<<gq, 256>>>(x, qw, qb, kw, kb, vw, vb);

    dim3 ga(SEQ / 32, NH, BD);               // (32, 16, 8)
    attn_kernel<<<ga, 256, ATTN_SMEM_BYTES>>>(probs);

    dim3 go(DIM / 128, MTOT / 128);          // (9, 64)
    oproj_kernel<<<go, 256>>>(ow, ob, out);
}

// round 3
// speedup vs baseline: 1.6522x; 1.6522x over previous
#include <cuda_runtime.h>
#include <math.h>

// ---------------------------------------------------------------------------
// SiglipAttention: B=8, N=1024, D=1152, H=16, Hd=72
// Outputs (concatenated in d_out): out [B,N,D] fp32, attn_probs [B,H,N,N] fp32
// ---------------------------------------------------------------------------

#define BD   8
#define SEQ  1024
#define DIM  1152
#define NH   16
#define HD   72
#define MTOT (BD * SEQ)                 // 8192
#define QKV_ELEMS (BD * NH * SEQ * HD)  // 9437184
#define OUT_ELEMS (BD * SEQ * DIM)      // 9437184
#define SCALE_F 0.117851130197757931f   // 72^-0.5

// Scratch (allocation-free rule: __device__ globals)
__device__ float g_q[QKV_ELEMS];    // [B,H,N,Hd]
__device__ float g_k[QKV_ELEMS];    // [B,H,N,Hd]
__device__ float g_v[QKV_ELEMS];    // [B,H,N,Hd]
__device__ float g_ctx[QKV_ELEMS];  // [B,H,N,Hd]

// ---------------------------------------------------------------------------
// Kernel 1: fused QKV projection.  y = x @ W^T + b  (NT SGEMM, both K-major)
// 128x128 block tile, BK=8, 256 threads, 8x8 microtile.
// blockIdx.z selects projection {q,k,v}; epilogue scatters to head layout
// [B,H,N,Hd] (all three identical now — no transposed K).
// ---------------------------------------------------------------------------
__global__ __launch_bounds__(256) void qkv_kernel(
    const float* __restrict__ x,
    const float* __restrict__ qw, const float* __restrict__ qb,
    const float* __restrict__ kw, const float* __restrict__ kb,
    const float* __restrict__ vw, const float* __restrict__ vb)
{
    const int proj = blockIdx.z;
    const float* w    = (proj == 0) ? qw : (proj == 1) ? kw : vw;
    const float* bias = (proj == 0) ? qb : (proj == 1) ? kb : vb;
    float* dst        = (proj == 0) ? g_q : (proj == 1) ? g_k : g_v;

    __shared__ float As[8][128];
    __shared__ float Bs[8][128];

    const int tid = threadIdx.x;
    const int tm = tid >> 4;         // 0..15
    const int tn = tid & 15;         // 0..15
    const int m0 = blockIdx.y * 128;
    const int n0 = blockIdx.x * 128;
    const int lr = tid >> 1;         // 0..127
    const int lk = (tid & 1) * 4;    // 0 or 4

    float acc[8][8];
#pragma unroll
    for (int i = 0; i < 8; i++)
#pragma unroll
        for (int j = 0; j < 8; j++) acc[i][j] = 0.f;

    for (int k0 = 0; k0 < DIM; k0 += 8) {
        float4 a4 = *(const float4*)(x + (size_t)(m0 + lr) * DIM + k0 + lk);
        float4 b4 = *(const float4*)(w + (size_t)(n0 + lr) * DIM + k0 + lk);
        __syncthreads();
        As[lk + 0][lr] = a4.x; As[lk + 1][lr] = a4.y;
        As[lk + 2][lr] = a4.z; As[lk + 3][lr] = a4.w;
        Bs[lk + 0][lr] = b4.x; Bs[lk + 1][lr] = b4.y;
        Bs[lk + 2][lr] = b4.z; Bs[lk + 3][lr] = b4.w;
        __syncthreads();
#pragma unroll
        for (int kk = 0; kk < 8; kk++) {
            float a[8], b[8];
            float4 t0 = *(const float4*)&As[kk][tm * 8];
            float4 t1 = *(const float4*)&As[kk][tm * 8 + 4];
            a[0]=t0.x; a[1]=t0.y; a[2]=t0.z; a[3]=t0.w;
            a[4]=t1.x; a[5]=t1.y; a[6]=t1.z; a[7]=t1.w;
            float4 u0 = *(const float4*)&Bs[kk][tn * 8];
            float4 u1 = *(const float4*)&Bs[kk][tn * 8 + 4];
            b[0]=u0.x; b[1]=u0.y; b[2]=u0.z; b[3]=u0.w;
            b[4]=u1.x; b[5]=u1.y; b[6]=u1.z; b[7]=u1.w;
#pragma unroll
            for (int i = 0; i < 8; i++)
#pragma unroll
                for (int j = 0; j < 8; j++) acc[i][j] += a[i] * b[j];
        }
    }

#pragma unroll
    for (int i = 0; i < 8; i++) {
        const int m = m0 + tm * 8 + i;
        const int bb = m >> 10;
        const int n  = m & 1023;
#pragma unroll
        for (int j = 0; j < 8; j++) {
            const int o  = n0 + tn * 8 + j;
            const int h  = o / HD;
            const int hd = o % HD;
            dst[((size_t)(bb * NH + h) * SEQ + n) * HD + hd] = acc[i][j] + bias[o];
        }
    }
}

// ---------------------------------------------------------------------------
// Kernel 2: scores GEMM.  S[b,h] = scale * Q[1024,72] @ K[1024,72]^T
// 128x128 output tile, K=72 loaded once into smem (no k-loop staging).
// smem tiles stored transposed [72][132] (pad 132 keeps LDS.128 alignment and
// reduces scatter-store conflicts).
// ---------------------------------------------------------------------------
#define SPAD 132
#define SCORES_SMEM_BYTES (2 * HD * SPAD * 4)   // 76032

__global__ __launch_bounds__(256) void scores_kernel(float* __restrict__ probs)
{
    extern __shared__ float sm[];
    float* As = sm;               // Q^T [72][132]
    float* Bs = sm + HD * SPAD;   // K^T [72][132]

    const int tid = threadIdx.x;
    const int tm = tid >> 4;      // 0..15
    const int tn = tid & 15;      // 0..15
    const int m0 = blockIdx.y * 128;
    const int n0 = blockIdx.x * 128;
    const int bh = blockIdx.z;

    const float* Qg = g_q + (size_t)bh * SEQ * HD;
    const float* Kg = g_k + (size_t)bh * SEQ * HD;

    // load Q tile (128 rows x 72) transposed into As, K tile into Bs
    for (int idx = tid; idx < 128 * 18; idx += 256) {
        const int row = idx / 18;
        const int c4  = (idx % 18) * 4;
        float4 qa = *(const float4*)(Qg + (size_t)(m0 + row) * HD + c4);
        float4 kb = *(const float4*)(Kg + (size_t)(n0 + row) * HD + c4);
        As[(c4 + 0) * SPAD + row] = qa.x; As[(c4 + 1) * SPAD + row] = qa.y;
        As[(c4 + 2) * SPAD + row] = qa.z; As[(c4 + 3) * SPAD + row] = qa.w;
        Bs[(c4 + 0) * SPAD + row] = kb.x; Bs[(c4 + 1) * SPAD + row] = kb.y;
        Bs[(c4 + 2) * SPAD + row] = kb.z; Bs[(c4 + 3) * SPAD + row] = kb.w;
    }
    __syncthreads();

    float acc[8][8];
#pragma unroll
    for (int i = 0; i < 8; i++)
#pragma unroll
        for (int j = 0; j < 8; j++) acc[i][j] = 0.f;

#pragma unroll 4
    for (int kk = 0; kk < HD; kk++) {
        float a[8], b[8];
        float4 t0 = *(const float4*)&As[kk * SPAD + tm * 8];
        float4 t1 = *(const float4*)&As[kk * SPAD + tm * 8 + 4];
        a[0]=t0.x; a[1]=t0.y; a[2]=t0.z; a[3]=t0.w;
        a[4]=t1.x; a[5]=t1.y; a[6]=t1.z; a[7]=t1.w;
        float4 u0 = *(const float4*)&Bs[kk * SPAD + tn * 8];
        float4 u1 = *(const float4*)&Bs[kk * SPAD + tn * 8 + 4];
        b[0]=u0.x; b[1]=u0.y; b[2]=u0.z; b[3]=u0.w;
        b[4]=u1.x; b[5]=u1.y; b[6]=u1.z; b[7]=u1.w;
#pragma unroll
        for (int i = 0; i < 8; i++)
#pragma unroll
            for (int j = 0; j < 8; j++) acc[i][j] += a[i] * b[j];
    }

    float* Sg = probs + (size_t)bh * SEQ * SEQ;
#pragma unroll
    for (int i = 0; i < 8; i++) {
        float4 w0, w1;
        w0.x = acc[i][0] * SCALE_F; w0.y = acc[i][1] * SCALE_F;
        w0.z = acc[i][2] * SCALE_F; w0.w = acc[i][3] * SCALE_F;
        w1.x = acc[i][4] * SCALE_F; w1.y = acc[i][5] * SCALE_F;
        w1.z = acc[i][6] * SCALE_F; w1.w = acc[i][7] * SCALE_F;
        float* p = Sg + (size_t)(m0 + tm * 8 + i) * SEQ + n0 + tn * 8;
        *(float4*)(p)     = w0;
        *(float4*)(p + 4) = w1;
    }
}

// ---------------------------------------------------------------------------
// Kernel 3: in-place row softmax over probs. One block per row (1024 floats),
// 256 threads x float4.
// ---------------------------------------------------------------------------
__global__ __launch_bounds__(256) void softmax_kernel(float* __restrict__ probs)
{
    __shared__ float red[8];
    const int tid = threadIdx.x;
    const int wid = tid >> 5, lane = tid & 31;
    float4* p = (float4*)(probs + (size_t)blockIdx.x * SEQ);

    float4 v = p[tid];
    float m = fmaxf(fmaxf(v.x, v.y), fmaxf(v.z, v.w));
#pragma unroll
    for (int o = 16; o; o >>= 1) m = fmaxf(m, __shfl_xor_sync(~0u, m, o));
    if (lane == 0) red[wid] = m;
    __syncthreads();
    m = fmaxf(fmaxf(fmaxf(red[0], red[1]), fmaxf(red[2], red[3])),
              fmaxf(fmaxf(red[4], red[5]), fmaxf(red[6], red[7])));

    v.x = __expf(v.x - m); v.y = __expf(v.y - m);
    v.z = __expf(v.z - m); v.w = __expf(v.w - m);
    float s = v.x + v.y + v.z + v.w;
#pragma unroll
    for (int o = 16; o; o >>= 1) s += __shfl_xor_sync(~0u, s, o);
    __syncthreads();
    if (lane == 0) red[wid] = s;
    __syncthreads();
    s = (red[0] + red[1] + red[2] + red[3]) +
        (red[4] + red[5] + red[6] + red[7]);
    const float inv = 1.f / s;
    v.x *= inv; v.y *= inv; v.z *= inv; v.w *= inv;
    p[tid] = v;
}

// ---------------------------------------------------------------------------
// Kernel 4: PV GEMM.  ctx[b,h] = P[1024,1024] @ V[1024,72]
// Tile 128q x 72hd, 288 threads (16x18), microtile 8x4, K staged in 64-chunks.
// ---------------------------------------------------------------------------
#define PV_KT 64
#define PV_SMEM_FLOATS (PV_KT * SPAD + PV_KT * HD)
#define PV_SMEM_BYTES  (PV_SMEM_FLOATS * 4)      // 52224

__global__ __launch_bounds__(288) void pv_kernel(const float* __restrict__ probs)
{
    extern __shared__ float sm[];
    float* Ps = sm;                  // P^T [64][132]
    float* Vs = sm + PV_KT * SPAD;   // V   [64][72]

    const int tid = threadIdx.x;
    const int tq = tid / 18;         // 0..15 -> query rows tq*8
    const int th = tid % 18;         // 0..17 -> hd cols th*4
    const int m0 = blockIdx.x * 128;
    const int bh = blockIdx.y;

    const float* Pg = probs + (size_t)bh * SEQ * SEQ;
    const float* Vg = g_v   + (size_t)bh * SEQ * HD;

    float acc[8][4];
#pragma unroll
    for (int i = 0; i < 8; i++)
#pragma unroll
        for (int j = 0; j < 4; j++) acc[i][j] = 0.f;

    for (int k0 = 0; k0 < SEQ; k0 += PV_KT) {
        __syncthreads();
        for (int idx = tid; idx < 128 * 16; idx += 288) {
            const int row = idx >> 4;
            const int c4  = (idx & 15) * 4;
            float4 pv = *(const float4*)(Pg + (size_t)(m0 + row) * SEQ + k0 + c4);
            Ps[(c4 + 0) * SPAD + row] = pv.x; Ps[(c4 + 1) * SPAD + row] = pv.y;
            Ps[(c4 + 2) * SPAD + row] = pv.z; Ps[(c4 + 3) * SPAD + row] = pv.w;
        }
        for (int idx = tid; idx < PV_KT * 18; idx += 288) {
            const int row = idx / 18;
            const int c4  = (idx % 18) * 4;
            *(float4*)(Vs + row * HD + c4) =
                *(const float4*)(Vg + (size_t)(k0 + row) * HD + c4);
        }
        __syncthreads();

#pragma unroll 4
        for (int kk = 0; kk < PV_KT; kk++) {
            float a[8], b[4];
            float4 t0 = *(const float4*)&Ps[kk * SPAD + tq * 8];
            float4 t1 = *(const float4*)&Ps[kk * SPAD + tq * 8 + 4];
            a[0]=t0.x; a[1]=t0.y; a[2]=t0.z; a[3]=t0.w;
            a[4]=t1.x; a[5]=t1.y; a[6]=t1.z; a[7]=t1.w;
            float4 u0 = *(const float4*)&Vs[kk * HD + th * 4];
            b[0]=u0.x; b[1]=u0.y; b[2]=u0.z; b[3]=u0.w;
#pragma unroll
            for (int i = 0; i < 8; i++)
#pragma unroll
                for (int j = 0; j < 4; j++) acc[i][j] += a[i] * b[j];
        }
    }

#pragma unroll
    for (int i = 0; i < 8; i++) {
        float4 w;
        w.x = acc[i][0]; w.y = acc[i][1]; w.z = acc[i][2]; w.w = acc[i][3];
        *(float4*)(g_ctx + ((size_t)bh * SEQ + m0 + tq * 8 + i) * HD + th * 4) = w;
    }
}

// ---------------------------------------------------------------------------
// Kernel 5: O projection.  out = ctx @ o_w^T + o_b
// Same SGEMM; A loads gather from head layout [B,H,N,Hd].
// ---------------------------------------------------------------------------
__global__ __launch_bounds__(256) void oproj_kernel(
    const float* __restrict__ ow, const float* __restrict__ ob,
    float* __restrict__ out)
{
    __shared__ float As[8][128];
    __shared__ float Bs[8][128];

    const int tid = threadIdx.x;
    const int tm = tid >> 4, tn = tid & 15;
    const int m0 = blockIdx.y * 128;
    const int n0 = blockIdx.x * 128;
    const int lr = tid >> 1;
    const int lk = (tid & 1) * 4;

    float acc[8][8];
#pragma unroll
    for (int i = 0; i < 8; i++)
#pragma unroll
        for (int j = 0; j < 8; j++) acc[i][j] = 0.f;

    const int m  = m0 + lr;
    const int bb = m >> 10;
    const int n  = m & 1023;

    for (int k0 = 0; k0 < DIM; k0 += 8) {
        const int k  = k0 + lk;
        const int h  = k / HD;
        const int hd = k % HD;
        float4 a4 = *(const float4*)(g_ctx + ((size_t)(bb * NH + h) * SEQ + n) * HD + hd);
        float4 b4 = *(const float4*)(ow + (size_t)(n0 + lr) * DIM + k0 + lk);
        __syncthreads();
        As[lk + 0][lr] = a4.x; As[lk + 1][lr] = a4.y;
        As[lk + 2][lr] = a4.z; As[lk + 3][lr] = a4.w;
        Bs[lk + 0][lr] = b4.x; Bs[lk + 1][lr] = b4.y;
        Bs[lk + 2][lr] = b4.z; Bs[lk + 3][lr] = b4.w;
        __syncthreads();
#pragma unroll
        for (int kk = 0; kk < 8; kk++) {
            float a[8], b[8];
            float4 t0 = *(const float4*)&As[kk][tm * 8];
            float4 t1 = *(const float4*)&As[kk][tm * 8 + 4];
            a[0]=t0.x; a[1]=t0.y; a[2]=t0.z; a[3]=t0.w;
            a[4]=t1.x; a[5]=t1.y; a[6]=t1.z; a[7]=t1.w;
            float4 u0 = *(const float4*)&Bs[kk][tn * 8];
            float4 u1 = *(const float4*)&Bs[kk][tn * 8 + 4];
            b[0]=u0.x; b[1]=u0.y; b[2]=u0.z; b[3]=u0.w;
            b[4]=u1.x; b[5]=u1.y; b[6]=u1.z; b[7]=u1.w;
#pragma unroll
            for (int i = 0; i < 8; i++)
#pragma unroll
                for (int j = 0; j < 8; j++) acc[i][j] += a[i] * b[j];
        }
    }

#pragma unroll
    for (int i = 0; i < 8; i++) {
        const int mm = m0 + tm * 8 + i;
#pragma unroll
        for (int j = 0; j < 8; j++) {
            const int o = n0 + tn * 8 + j;
            out[(size_t)mm * DIM + o] = acc[i][j] + ob[o];
        }
    }
}

// ---------------------------------------------------------------------------
extern "C" void kernel_launch(void* const* d_in, const int* in_sizes, int n_in,
                              void* d_out, int out_size)
{
    const float* x  = (const float*)d_in[0];
    const float* qw = (const float*)d_in[1];
    const float* qb = (const float*)d_in[2];
    const float* kw = (const float*)d_in[3];
    const float* kb = (const float*)d_in[4];
    const float* vw = (const float*)d_in[5];
    const float* vb = (const float*)d_in[6];
    const float* ow = (const float*)d_in[7];
    const float* ob = (const float*)d_in[8];

    float* out   = (float*)d_out;            // [B,N,D]
    float* probs = out + OUT_ELEMS;          // [B,H,N,N]

    cudaFuncSetAttribute(scores_kernel,
                         cudaFuncAttributeMaxDynamicSharedMemorySize,
                         SCORES_SMEM_BYTES);
    cudaFuncSetAttribute(pv_kernel,
                         cudaFuncAttributeMaxDynamicSharedMemorySize,
                         PV_SMEM_BYTES);

    dim3 gq(DIM / 128, MTOT / 128, 3);       // (9, 64, 3)
    qkv_kernel<<<gq, 256>>>(x, qw, qb, kw, kb, vw, vb);

    dim3 gs(SEQ / 128, SEQ / 128, BD * NH);  // (8, 8, 128)
    scores_kernel<<<gs, 256, SCORES_SMEM_BYTES>>>(probs);

    softmax_kernel<<<BD * NH * SEQ, 256>>>(probs);

    dim3 gp(SEQ / 128, BD * NH);             // (8, 128)
    pv_kernel<<<gp, 288, PV_SMEM_BYTES>>>(probs);

    dim3 go(DIM / 128, MTOT / 128);          // (9, 64)
    oproj_kernel<<<go, 256>>>(ow, ob, out);
}

// round 5
// speedup vs baseline: 2.3527x; 1.4240x over previous
#include <cuda_runtime.h>
#include <cuda_bf16.h>
#include <cstdint>
#include <math.h>

// ---------------------------------------------------------------------------
// SiglipAttention: B=8, N=1024, D=1152, H=16, Hd=72
// Outputs (concatenated in d_out): out [B,N,D] fp32, attn_probs [B,H,N,N] fp32
// ---------------------------------------------------------------------------

#define BD   8
#define SEQ  1024
#define DIM  1152
#define NH   16
#define HD   72
#define MTOT (BD * SEQ)                 // 8192
#define QKV_ELEMS (BD * NH * SEQ * HD)  // 9437184
#define OUT_ELEMS (BD * SEQ * DIM)      // 9437184
#define SCALE_F 0.117851130197757931f   // 72^-0.5

// Scratch (allocation-free rule: __device__ globals)
__device__ float g_q[QKV_ELEMS];    // [B,H,N,Hd]
__device__ float g_k[QKV_ELEMS];    // [B,H,N,Hd]
__device__ float g_v[QKV_ELEMS];    // [B,H,N,Hd]
__device__ float g_ctx[OUT_ELEMS];  // [B,N,D]  (row layout for O-proj)

// ===========================================================================
// HMMA helpers (sm_80+ mma.sync path — tcgen05 unavailable: harness PTX
// targets sm_103 base, not sm_103a)
// ===========================================================================
__device__ __forceinline__ uint32_t smem_u32(const void* p) {
    uint32_t a;
    asm("{ .reg .u64 t; cvta.to.shared.u64 t, %1; cvt.u32.u64 %0, t; }"
        : "=r"(a) : "l"(p));
    return a;
}

__device__ __forceinline__ void ldsm_x4(uint32_t& r0, uint32_t& r1,
                                        uint32_t& r2, uint32_t& r3, uint32_t a) {
    asm volatile("ldmatrix.sync.aligned.m8n8.x4.shared.b16 {%0,%1,%2,%3}, [%4];"
                 : "=r"(r0), "=r"(r1), "=r"(r2), "=r"(r3) : "r"(a));
}
__device__ __forceinline__ void ldsm_x2(uint32_t& r0, uint32_t& r1, uint32_t a) {
    asm volatile("ldmatrix.sync.aligned.m8n8.x2.shared.b16 {%0,%1}, [%2];"
                 : "=r"(r0), "=r"(r1) : "r"(a));
}
__device__ __forceinline__ void mma16816(float* c,
                                         uint32_t a0, uint32_t a1, uint32_t a2, uint32_t a3,
                                         uint32_t b0, uint32_t b1) {
    asm volatile(
        "mma.sync.aligned.m16n8k16.row.col.f32.bf16.bf16.f32 "
        "{%0,%1,%2,%3}, {%4,%5,%6,%7}, {%8,%9}, {%0,%1,%2,%3};"
        : "+f"(c[0]), "+f"(c[1]), "+f"(c[2]), "+f"(c[3])
        : "r"(a0), "r"(a1), "r"(a2), "r"(a3), "r"(b0), "r"(b1));
}

// split fp32x4 -> hi bf16x4 + lo bf16x4 (packed as uint2 each)
__device__ __forceinline__ void split8(uint2& hi, uint2& lo, float4 v) {
    __nv_bfloat162 h01 = __floats2bfloat162_rn(v.x, v.y);
    __nv_bfloat162 h23 = __floats2bfloat162_rn(v.z, v.w);
    float rx = v.x - __bfloat162float(h01.x);
    float ry = v.y - __bfloat162float(h01.y);
    float rz = v.z - __bfloat162float(h23.x);
    float rw = v.w - __bfloat162float(h23.y);
    hi = make_uint2(*(uint32_t*)&h01, *(uint32_t*)&h23);
    __nv_bfloat162 l01 = __floats2bfloat162_rn(rx, ry);
    __nv_bfloat162 l23 = __floats2bfloat162_rn(rz, rw);
    lo = make_uint2(*(uint32_t*)&l01, *(uint32_t*)&l23);
}

// ===========================================================================
// Common bf16x3 HMMA GEMM device core:  y[128,128]tile = A[M,K] @ W[N,K]^T
// K consumed in chunks of 32.  MODE 0: head-scatter epilogue (qkv);
// MODE 1: plain [M,DIM] epilogue (o-proj).
// smem tiles [128][40] bf16 (80B stride -> conflict-free ldmatrix).
// ===========================================================================
#define TSTR 40   // bf16 elements per smem row (80 bytes)

template <int MODE>
__device__ __forceinline__ void tc_gemm_tile(
    const float* __restrict__ A, const float* __restrict__ W,
    const float* __restrict__ bias, float* __restrict__ dst,
    int m0, int n0)
{
    __shared__ __nv_bfloat16 sAh[128 * TSTR], sAl[128 * TSTR];
    __shared__ __nv_bfloat16 sBh[128 * TSTR], sBl[128 * TSTR];

    const int tid  = threadIdx.x;
    const int lane = tid & 31;
    const int wid  = tid >> 5;
    const int wm   = (wid >> 2) * 64;   // warp m-offset (0/64)
    const int wn   = (wid & 3) * 32;    // warp n-offset (0/32/64/96)

    const uint32_t ah = smem_u32(sAh), al = smem_u32(sAl);
    const uint32_t bh = smem_u32(sBh), bl = smem_u32(sBl);

    float acc[4][4][4];
#pragma unroll
    for (int i = 0; i < 4; i++)
#pragma unroll
        for (int j = 0; j < 4; j++)
#pragma unroll
            for (int q = 0; q < 4; q++) acc[i][j][q] = 0.f;

    // per-lane ldmatrix address components
    const uint32_t a_row = wm + (lane & 15);
    const uint32_t a_off = a_row * (TSTR * 2) + (lane >> 4) * 16;
    const uint32_t b_row_base = wn + (lane & 7);
    const uint32_t b_off = ((lane >> 3) & 1) * 16;

    for (int k0 = 0; k0 < DIM; k0 += 32) {
        __syncthreads();
        // stage A and W 128x32 fp32 -> hi/lo bf16 (4 float4 each per thread)
#pragma unroll
        for (int t = 0; t < 4; t++) {
            const int idx = tid + t * 256;         // 0..1023
            const int row = idx >> 3;
            const int c4  = (idx & 7) << 2;
            float4 av = *(const float4*)(A + (size_t)(m0 + row) * DIM + k0 + c4);
            float4 wv = *(const float4*)(W + (size_t)(n0 + row) * DIM + k0 + c4);
            uint2 h, l;
            split8(h, l, av);
            *(uint2*)(sAh + row * TSTR + c4) = h;
            *(uint2*)(sAl + row * TSTR + c4) = l;
            split8(h, l, wv);
            *(uint2*)(sBh + row * TSTR + c4) = h;
            *(uint2*)(sBl + row * TSTR + c4) = l;
        }
        __syncthreads();

#pragma unroll
        for (int ks = 0; ks < 2; ks++) {
            uint32_t Ah[4][4], Al[4][4], Bh[4][2], Bl[4][2];
#pragma unroll
            for (int mf = 0; mf < 4; mf++) {
                const uint32_t addr = a_off + mf * 16 * (TSTR * 2) + ks * 32;
                ldsm_x4(Ah[mf][0], Ah[mf][1], Ah[mf][2], Ah[mf][3], ah + addr);
                ldsm_x4(Al[mf][0], Al[mf][1], Al[mf][2], Al[mf][3], al + addr);
            }
#pragma unroll
            for (int nf = 0; nf < 4; nf++) {
                const uint32_t addr = (b_row_base + nf * 8) * (TSTR * 2) + ks * 32 + b_off;
                ldsm_x2(Bh[nf][0], Bh[nf][1], bh + addr);
                ldsm_x2(Bl[nf][0], Bl[nf][1], bl + addr);
            }
#pragma unroll
            for (int mf = 0; mf < 4; mf++)
#pragma unroll
                for (int nf = 0; nf < 4; nf++) {
                    mma16816(acc[mf][nf], Ah[mf][0], Ah[mf][1], Ah[mf][2], Ah[mf][3],
                             Bh[nf][0], Bh[nf][1]);
                    mma16816(acc[mf][nf], Al[mf][0], Al[mf][1], Al[mf][2], Al[mf][3],
                             Bh[nf][0], Bh[nf][1]);
                    mma16816(acc[mf][nf], Ah[mf][0], Ah[mf][1], Ah[mf][2], Ah[mf][3],
                             Bl[nf][0], Bl[nf][1]);
                }
        }
    }

    // epilogue
    const int r_base = m0 + wm + (lane >> 2);
    const int c_base = n0 + wn + (lane & 3) * 2;
#pragma unroll
    for (int mf = 0; mf < 4; mf++) {
#pragma unroll
        for (int nf = 0; nf < 4; nf++) {
            const int col = c_base + nf * 8;
            const float bx = bias[col], by = bias[col + 1];
#pragma unroll
            for (int half = 0; half < 2; half++) {
                const int row = r_base + mf * 16 + half * 8;
                float2 v;
                v.x = acc[mf][nf][half * 2 + 0] + bx;
                v.y = acc[mf][nf][half * 2 + 1] + by;
                if (MODE == 0) {
                    const int bb = row >> 10, n = row & 1023;
                    const int h = col / HD, hd = col % HD;
                    *(float2*)(dst + ((size_t)(bb * NH + h) * SEQ + n) * HD + hd) = v;
                } else {
                    *(float2*)(dst + (size_t)row * DIM + col) = v;
                }
            }
        }
    }
}

// Kernel 1: QKV projection (z picks proj, head-scatter epilogue)
__global__ __launch_bounds__(256) void qkv_tc_kernel(
    const float* __restrict__ x,
    const float* __restrict__ qw, const float* __restrict__ qb,
    const float* __restrict__ kw, const float* __restrict__ kb,
    const float* __restrict__ vw, const float* __restrict__ vb)
{
    const int proj = blockIdx.z;
    const float* w    = (proj == 0) ? qw : (proj == 1) ? kw : vw;
    const float* bias = (proj == 0) ? qb : (proj == 1) ? kb : vb;
    float* dst        = (proj == 0) ? g_q : (proj == 1) ? g_k : g_v;
    tc_gemm_tile<0>(x, w, bias, dst, blockIdx.y * 128, blockIdx.x * 128);
}

// Kernel 5: O projection (plain epilogue, A = ctx in [M,DIM])
__global__ __launch_bounds__(256) void oproj_tc_kernel(
    const float* __restrict__ ow, const float* __restrict__ ob,
    float* __restrict__ out)
{
    tc_gemm_tile<1>(g_ctx, ow, ob, out, blockIdx.y * 128, blockIdx.x * 128);
}

// ---------------------------------------------------------------------------
// Kernel 2: scores GEMM.  S[b,h] = scale * Q[1024,72] @ K[1024,72]^T
// ---------------------------------------------------------------------------
#define SPAD 132
#define SCORES_SMEM_BYTES (2 * HD * SPAD * 4)   // 76032

__global__ __launch_bounds__(256) void scores_kernel(float* __restrict__ probs)
{
    extern __shared__ float sm[];
    float* As = sm;               // Q^T [72][132]
    float* Bs = sm + HD * SPAD;   // K^T [72][132]

    const int tid = threadIdx.x;
    const int tm = tid >> 4;      // 0..15
    const int tn = tid & 15;      // 0..15
    const int m0 = blockIdx.y * 128;
    const int n0 = blockIdx.x * 128;
    const int bh = blockIdx.z;

    const float* Qg = g_q + (size_t)bh * SEQ * HD;
    const float* Kg = g_k + (size_t)bh * SEQ * HD;

    for (int idx = tid; idx < 128 * 18; idx += 256) {
        const int row = idx / 18;
        const int c4  = (idx % 18) * 4;
        float4 qa = *(const float4*)(Qg + (size_t)(m0 + row) * HD + c4);
        float4 kb = *(const float4*)(Kg + (size_t)(n0 + row) * HD + c4);
        As[(c4 + 0) * SPAD + row] = qa.x; As[(c4 + 1) * SPAD + row] = qa.y;
        As[(c4 + 2) * SPAD + row] = qa.z; As[(c4 + 3) * SPAD + row] = qa.w;
        Bs[(c4 + 0) * SPAD + row] = kb.x; Bs[(c4 + 1) * SPAD + row] = kb.y;
        Bs[(c4 + 2) * SPAD + row] = kb.z; Bs[(c4 + 3) * SPAD + row] = kb.w;
    }
    __syncthreads();

    float acc[8][8];
#pragma unroll
    for (int i = 0; i < 8; i++)
#pragma unroll
        for (int j = 0; j < 8; j++) acc[i][j] = 0.f;

#pragma unroll 4
    for (int kk = 0; kk < HD; kk++) {
        float a[8], b[8];
        float4 t0 = *(const float4*)&As[kk * SPAD + tm * 8];
        float4 t1 = *(const float4*)&As[kk * SPAD + tm * 8 + 4];
        a[0]=t0.x; a[1]=t0.y; a[2]=t0.z; a[3]=t0.w;
        a[4]=t1.x; a[5]=t1.y; a[6]=t1.z; a[7]=t1.w;
        float4 u0 = *(const float4*)&Bs[kk * SPAD + tn * 8];
        float4 u1 = *(const float4*)&Bs[kk * SPAD + tn * 8 + 4];
        b[0]=u0.x; b[1]=u0.y; b[2]=u0.z; b[3]=u0.w;
        b[4]=u1.x; b[5]=u1.y; b[6]=u1.z; b[7]=u1.w;
#pragma unroll
        for (int i = 0; i < 8; i++)
#pragma unroll
            for (int j = 0; j < 8; j++) acc[i][j] += a[i] * b[j];
    }

    float* Sg = probs + (size_t)bh * SEQ * SEQ;
#pragma unroll
    for (int i = 0; i < 8; i++) {
        float4 w0, w1;
        w0.x = acc[i][0] * SCALE_F; w0.y = acc[i][1] * SCALE_F;
        w0.z = acc[i][2] * SCALE_F; w0.w = acc[i][3] * SCALE_F;
        w1.x = acc[i][4] * SCALE_F; w1.y = acc[i][5] * SCALE_F;
        w1.z = acc[i][6] * SCALE_F; w1.w = acc[i][7] * SCALE_F;
        float* p = Sg + (size_t)(m0 + tm * 8 + i) * SEQ + n0 + tn * 8;
        *(float4*)(p)     = w0;
        *(float4*)(p + 4) = w1;
    }
}

// ---------------------------------------------------------------------------
// Kernel 3: in-place row softmax over probs.
// ---------------------------------------------------------------------------
__global__ __launch_bounds__(256) void softmax_kernel(float* __restrict__ probs)
{
    __shared__ float red[8];
    const int tid = threadIdx.x;
    const int wid = tid >> 5, lane = tid & 31;
    float4* p = (float4*)(probs + (size_t)blockIdx.x * SEQ);

    float4 v = p[tid];
    float m = fmaxf(fmaxf(v.x, v.y), fmaxf(v.z, v.w));
#pragma unroll
    for (int o = 16; o; o >>= 1) m = fmaxf(m, __shfl_xor_sync(~0u, m, o));
    if (lane == 0) red[wid] = m;
    __syncthreads();
    m = fmaxf(fmaxf(fmaxf(red[0], red[1]), fmaxf(red[2], red[3])),
              fmaxf(fmaxf(red[4], red[5]), fmaxf(red[6], red[7])));

    v.x = __expf(v.x - m); v.y = __expf(v.y - m);
    v.z = __expf(v.z - m); v.w = __expf(v.w - m);
    float s = v.x + v.y + v.z + v.w;
#pragma unroll
    for (int o = 16; o; o >>= 1) s += __shfl_xor_sync(~0u, s, o);
    __syncthreads();
    if (lane == 0) red[wid] = s;
    __syncthreads();
    s = (red[0] + red[1] + red[2] + red[3]) +
        (red[4] + red[5] + red[6] + red[7]);
    const float inv = 1.f / s;
    v.x *= inv; v.y *= inv; v.z *= inv; v.w *= inv;
    p[tid] = v;
}

// ---------------------------------------------------------------------------
// Kernel 4: PV GEMM.  ctx = P[1024,1024] @ V[1024,72]  -> [B,N,D] layout
// ---------------------------------------------------------------------------
#define PV_KT 64
#define PV_SMEM_FLOATS (PV_KT * SPAD + PV_KT * HD)
#define PV_SMEM_BYTES  (PV_SMEM_FLOATS * 4)      // 52224

__global__ __launch_bounds__(288) void pv_kernel(const float* __restrict__ probs)
{
    extern __shared__ float sm[];
    float* Ps = sm;                  // P^T [64][132]
    float* Vs = sm + PV_KT * SPAD;   // V   [64][72]

    const int tid = threadIdx.x;
    const int tq = tid / 18;         // 0..15
    const int th = tid % 18;         // 0..17
    const int m0 = blockIdx.x * 128;
    const int bh = blockIdx.y;
    const int bb = bh >> 4, hh = bh & 15;

    const float* Pg = probs + (size_t)bh * SEQ * SEQ;
    const float* Vg = g_v   + (size_t)bh * SEQ * HD;

    float acc[8][4];
#pragma unroll
    for (int i = 0; i < 8; i++)
#pragma unroll
        for (int j = 0; j < 4; j++) acc[i][j] = 0.f;

    for (int k0 = 0; k0 < SEQ; k0 += PV_KT) {
        __syncthreads();
        for (int idx = tid; idx < 128 * 16; idx += 288) {
            const int row = idx >> 4;
            const int c4  = (idx & 15) * 4;
            float4 pv = *(const float4*)(Pg + (size_t)(m0 + row) * SEQ + k0 + c4);
            Ps[(c4 + 0) * SPAD + row] = pv.x; Ps[(c4 + 1) * SPAD + row] = pv.y;
            Ps[(c4 + 2) * SPAD + row] = pv.z; Ps[(c4 + 3) * SPAD + row] = pv.w;
        }
        for (int idx = tid; idx < PV_KT * 18; idx += 288) {
            const int row = idx / 18;
            const int c4  = (idx % 18) * 4;
            *(float4*)(Vs + row * HD + c4) =
                *(const float4*)(Vg + (size_t)(k0 + row) * HD + c4);
        }
        __syncthreads();

#pragma unroll 4
        for (int kk = 0; kk < PV_KT; kk++) {
            float a[8], b[4];
            float4 t0 = *(const float4*)&Ps[kk * SPAD + tq * 8];
            float4 t1 = *(const float4*)&Ps[kk * SPAD + tq * 8 + 4];
            a[0]=t0.x; a[1]=t0.y; a[2]=t0.z; a[3]=t0.w;
            a[4]=t1.x; a[5]=t1.y; a[6]=t1.z; a[7]=t1.w;
            float4 u0 = *(const float4*)&Vs[kk * HD + th * 4];
            b[0]=u0.x; b[1]=u0.y; b[2]=u0.z; b[3]=u0.w;
#pragma unroll
            for (int i = 0; i < 8; i++)
#pragma unroll
                for (int j = 0; j < 4; j++) acc[i][j] += a[i] * b[j];
        }
    }

    // write to [B,N,D] row layout (hd contiguous)
#pragma unroll
    for (int i = 0; i < 8; i++) {
        float4 w;
        w.x = acc[i][0]; w.y = acc[i][1]; w.z = acc[i][2]; w.w = acc[i][3];
        *(float4*)(g_ctx + ((size_t)bb * SEQ + m0 + tq * 8 + i) * DIM
                   + hh * HD + th * 4) = w;
    }
}

// ---------------------------------------------------------------------------
extern "C" void kernel_launch(void* const* d_in, const int* in_sizes, int n_in,
                              void* d_out, int out_size)
{
    const float* x  = (const float*)d_in[0];
    const float* qw = (const float*)d_in[1];
    const float* qb = (const float*)d_in[2];
    const float* kw = (const float*)d_in[3];
    const float* kb = (const float*)d_in[4];
    const float* vw = (const float*)d_in[5];
    const float* vb = (const float*)d_in[6];
    const float* ow = (const float*)d_in[7];
    const float* ob = (const float*)d_in[8];

    float* out   = (float*)d_out;            // [B,N,D]
    float* probs = out + OUT_ELEMS;          // [B,H,N,N]

    cudaFuncSetAttribute(scores_kernel,
                         cudaFuncAttributeMaxDynamicSharedMemorySize,
                         SCORES_SMEM_BYTES);
    cudaFuncSetAttribute(pv_kernel,
                         cudaFuncAttributeMaxDynamicSharedMemorySize,
                         PV_SMEM_BYTES);

    dim3 gq(DIM / 128, MTOT / 128, 3);       // (9, 64, 3)
    qkv_tc_kernel<<<gq, 256>>>(x, qw, qb, kw, kb, vw, vb);

    dim3 gs(SEQ / 128, SEQ / 128, BD * NH);  // (8, 8, 128)
    scores_kernel<<<gs, 256, SCORES_SMEM_BYTES>>>(probs);

    softmax_kernel<<<BD * NH * SEQ, 256>>>(probs);

    dim3 gp(SEQ / 128, BD * NH);             // (8, 128)
    pv_kernel<<<gp, 288, PV_SMEM_BYTES>>>(probs);

    dim3 go(DIM / 128, MTOT / 128);          // (9, 64)
    oproj_tc_kernel<<<go, 256>>>(ow, ob, out);
}

// round 6
// speedup vs baseline: 2.6840x; 1.1409x over previous
#include <cuda_runtime.h>
#include <cuda_bf16.h>
#include <cstdint>
#include <math.h>

// ---------------------------------------------------------------------------
// SiglipAttention: B=8, N=1024, D=1152, H=16, Hd=72
// Outputs (concatenated in d_out): out [B,N,D] fp32, attn_probs [B,H,N,N] fp32
// ---------------------------------------------------------------------------

#define BD   8
#define SEQ  1024
#define DIM  1152
#define NH   16
#define HD   72
#define MTOT (BD * SEQ)                 // 8192
#define QKV_ELEMS (BD * NH * SEQ * HD)  // 9437184
#define OUT_ELEMS (BD * SEQ * DIM)      // 9437184
#define SCALE_F 0.117851130197757931f   // 72^-0.5

// Scratch (allocation-free rule: __device__ globals)
__device__ float g_q[QKV_ELEMS];    // [B,H,N,Hd]
__device__ float g_k[QKV_ELEMS];    // [B,H,N,Hd]
__device__ float g_v[QKV_ELEMS];    // [B,H,N,Hd]
__device__ float g_ctx[OUT_ELEMS];  // [B,N,D]  (row layout for O-proj)

// ===========================================================================
// HMMA helpers (sm_80+ mma.sync path — tcgen05 unavailable: harness PTX
// targets sm_103 base, not sm_103a)
// ===========================================================================
__device__ __forceinline__ uint32_t smem_u32(const void* p) {
    uint32_t a;
    asm("{ .reg .u64 t; cvta.to.shared.u64 t, %1; cvt.u32.u64 %0, t; }"
        : "=r"(a) : "l"(p));
    return a;
}

__device__ __forceinline__ void ldsm_x4(uint32_t& r0, uint32_t& r1,
                                        uint32_t& r2, uint32_t& r3, uint32_t a) {
    asm volatile("ldmatrix.sync.aligned.m8n8.x4.shared.b16 {%0,%1,%2,%3}, [%4];"
                 : "=r"(r0), "=r"(r1), "=r"(r2), "=r"(r3) : "r"(a));
}
__device__ __forceinline__ void ldsm_x2(uint32_t& r0, uint32_t& r1, uint32_t a) {
    asm volatile("ldmatrix.sync.aligned.m8n8.x2.shared.b16 {%0,%1}, [%2];"
                 : "=r"(r0), "=r"(r1) : "r"(a));
}
__device__ __forceinline__ void mma16816(float* c,
                                         uint32_t a0, uint32_t a1, uint32_t a2, uint32_t a3,
                                         uint32_t b0, uint32_t b1) {
    asm volatile(
        "mma.sync.aligned.m16n8k16.row.col.f32.bf16.bf16.f32 "
        "{%0,%1,%2,%3}, {%4,%5,%6,%7}, {%8,%9}, {%0,%1,%2,%3};"
        : "+f"(c[0]), "+f"(c[1]), "+f"(c[2]), "+f"(c[3])
        : "r"(a0), "r"(a1), "r"(a2), "r"(a3), "r"(b0), "r"(b1));
}

// split fp32x4 -> hi bf16x4 + lo bf16x4 (packed as uint2 each)
__device__ __forceinline__ void split8(uint2& hi, uint2& lo, float4 v) {
    __nv_bfloat162 h01 = __floats2bfloat162_rn(v.x, v.y);
    __nv_bfloat162 h23 = __floats2bfloat162_rn(v.z, v.w);
    float rx = v.x - __bfloat162float(h01.x);
    float ry = v.y - __bfloat162float(h01.y);
    float rz = v.z - __bfloat162float(h23.x);
    float rw = v.w - __bfloat162float(h23.y);
    hi = make_uint2(*(uint32_t*)&h01, *(uint32_t*)&h23);
    __nv_bfloat162 l01 = __floats2bfloat162_rn(rx, ry);
    __nv_bfloat162 l23 = __floats2bfloat162_rn(rz, rw);
    lo = make_uint2(*(uint32_t*)&l01, *(uint32_t*)&l23);
}

// split fp32x4 -> 4 separate hi bf16 + 4 lo bf16 (for transposed scatter)
__device__ __forceinline__ void split4s(float4 v,
                                        __nv_bfloat16* hi, __nv_bfloat16* lo) {
    hi[0] = __float2bfloat16_rn(v.x);
    hi[1] = __float2bfloat16_rn(v.y);
    hi[2] = __float2bfloat16_rn(v.z);
    hi[3] = __float2bfloat16_rn(v.w);
    lo[0] = __float2bfloat16_rn(v.x - __bfloat162float(hi[0]));
    lo[1] = __float2bfloat16_rn(v.y - __bfloat162float(hi[1]));
    lo[2] = __float2bfloat16_rn(v.z - __bfloat162float(hi[2]));
    lo[3] = __float2bfloat16_rn(v.w - __bfloat162float(hi[3]));
}

// ===========================================================================
// Common bf16x3 HMMA GEMM device core:  y[128,128]tile = A[M,K] @ W[N,K]^T
// K consumed in chunks of 32.  MODE 0: head-scatter epilogue (qkv);
// MODE 1: plain [M,DIM] epilogue (o-proj).
// smem tiles [128][40] bf16 (80B stride -> conflict-free ldmatrix).
// ===========================================================================
#define TSTR 40   // bf16 elements per smem row (80 bytes)

template <int MODE>
__device__ __forceinline__ void tc_gemm_tile(
    const float* __restrict__ A, const float* __restrict__ W,
    const float* __restrict__ bias, float* __restrict__ dst,
    int m0, int n0)
{
    __shared__ __nv_bfloat16 sAh[128 * TSTR], sAl[128 * TSTR];
    __shared__ __nv_bfloat16 sBh[128 * TSTR], sBl[128 * TSTR];

    const int tid  = threadIdx.x;
    const int lane = tid & 31;
    const int wid  = tid >> 5;
    const int wm   = (wid >> 2) * 64;   // warp m-offset (0/64)
    const int wn   = (wid & 3) * 32;    // warp n-offset (0/32/64/96)

    const uint32_t ah = smem_u32(sAh), al = smem_u32(sAl);
    const uint32_t bh = smem_u32(sBh), bl = smem_u32(sBl);

    float acc[4][4][4];
#pragma unroll
    for (int i = 0; i < 4; i++)
#pragma unroll
        for (int j = 0; j < 4; j++)
#pragma unroll
            for (int q = 0; q < 4; q++) acc[i][j][q] = 0.f;

    const uint32_t a_row = wm + (lane & 15);
    const uint32_t a_off = a_row * (TSTR * 2) + (lane >> 4) * 16;
    const uint32_t b_row_base = wn + (lane & 7);
    const uint32_t b_off = ((lane >> 3) & 1) * 16;

    for (int k0 = 0; k0 < DIM; k0 += 32) {
        __syncthreads();
#pragma unroll
        for (int t = 0; t < 4; t++) {
            const int idx = tid + t * 256;         // 0..1023
            const int row = idx >> 3;
            const int c4  = (idx & 7) << 2;
            float4 av = *(const float4*)(A + (size_t)(m0 + row) * DIM + k0 + c4);
            float4 wv = *(const float4*)(W + (size_t)(n0 + row) * DIM + k0 + c4);
            uint2 h, l;
            split8(h, l, av);
            *(uint2*)(sAh + row * TSTR + c4) = h;
            *(uint2*)(sAl + row * TSTR + c4) = l;
            split8(h, l, wv);
            *(uint2*)(sBh + row * TSTR + c4) = h;
            *(uint2*)(sBl + row * TSTR + c4) = l;
        }
        __syncthreads();

#pragma unroll
        for (int ks = 0; ks < 2; ks++) {
            uint32_t Ah[4][4], Al[4][4], Bh[4][2], Bl[4][2];
#pragma unroll
            for (int mf = 0; mf < 4; mf++) {
                const uint32_t addr = a_off + mf * 16 * (TSTR * 2) + ks * 32;
                ldsm_x4(Ah[mf][0], Ah[mf][1], Ah[mf][2], Ah[mf][3], ah + addr);
                ldsm_x4(Al[mf][0], Al[mf][1], Al[mf][2], Al[mf][3], al + addr);
            }
#pragma unroll
            for (int nf = 0; nf < 4; nf++) {
                const uint32_t addr = (b_row_base + nf * 8) * (TSTR * 2) + ks * 32 + b_off;
                ldsm_x2(Bh[nf][0], Bh[nf][1], bh + addr);
                ldsm_x2(Bl[nf][0], Bl[nf][1], bl + addr);
            }
#pragma unroll
            for (int mf = 0; mf < 4; mf++)
#pragma unroll
                for (int nf = 0; nf < 4; nf++) {
                    mma16816(acc[mf][nf], Ah[mf][0], Ah[mf][1], Ah[mf][2], Ah[mf][3],
                             Bh[nf][0], Bh[nf][1]);
                    mma16816(acc[mf][nf], Al[mf][0], Al[mf][1], Al[mf][2], Al[mf][3],
                             Bh[nf][0], Bh[nf][1]);
                    mma16816(acc[mf][nf], Ah[mf][0], Ah[mf][1], Ah[mf][2], Ah[mf][3],
                             Bl[nf][0], Bl[nf][1]);
                }
        }
    }

    const int r_base = m0 + wm + (lane >> 2);
    const int c_base = n0 + wn + (lane & 3) * 2;
#pragma unroll
    for (int mf = 0; mf < 4; mf++) {
#pragma unroll
        for (int nf = 0; nf < 4; nf++) {
            const int col = c_base + nf * 8;
            const float bx = bias[col], by = bias[col + 1];
#pragma unroll
            for (int half = 0; half < 2; half++) {
                const int row = r_base + mf * 16 + half * 8;
                float2 v;
                v.x = acc[mf][nf][half * 2 + 0] + bx;
                v.y = acc[mf][nf][half * 2 + 1] + by;
                if (MODE == 0) {
                    const int bb = row >> 10, n = row & 1023;
                    const int h = col / HD, hd = col % HD;
                    *(float2*)(dst + ((size_t)(bb * NH + h) * SEQ + n) * HD + hd) = v;
                } else {
                    *(float2*)(dst + (size_t)row * DIM + col) = v;
                }
            }
        }
    }
}

// Kernel 1: QKV projection (z picks proj, head-scatter epilogue)
__global__ __launch_bounds__(256) void qkv_tc_kernel(
    const float* __restrict__ x,
    const float* __restrict__ qw, const float* __restrict__ qb,
    const float* __restrict__ kw, const float* __restrict__ kb,
    const float* __restrict__ vw, const float* __restrict__ vb)
{
    const int proj = blockIdx.z;
    const float* w    = (proj == 0) ? qw : (proj == 1) ? kw : vw;
    const float* bias = (proj == 0) ? qb : (proj == 1) ? kb : vb;
    float* dst        = (proj == 0) ? g_q : (proj == 1) ? g_k : g_v;
    tc_gemm_tile<0>(x, w, bias, dst, blockIdx.y * 128, blockIdx.x * 128);
}

// Kernel 5: O projection (plain epilogue, A = ctx in [M,DIM])
__global__ __launch_bounds__(256) void oproj_tc_kernel(
    const float* __restrict__ ow, const float* __restrict__ ob,
    float* __restrict__ out)
{
    tc_gemm_tile<1>(g_ctx, ow, ob, out, blockIdx.y * 128, blockIdx.x * 128);
}

// ===========================================================================
// Kernel 2: scores GEMM on HMMA bf16x3.
//   S[b,h] = scale * Q[1024,72] @ K[1024,72]^T, 128x128 tile per CTA.
//   K-dim 72 zero-padded to 80; single smem stage; row stride 88 bf16
//   (176B == 12 banks mod 32 -> 8 ldmatrix rows conflict-free).
// ===========================================================================
#define SC_TS 88
#define SC_TILE (128 * SC_TS)
#define SCORES_SMEM_BYTES (4 * SC_TILE * 2)   // 90112

__global__ __launch_bounds__(256) void scores_tc_kernel(float* __restrict__ probs)
{
    extern __shared__ __nv_bfloat16 sc_sm[];
    __nv_bfloat16* sQh = sc_sm;
    __nv_bfloat16* sQl = sc_sm + SC_TILE;
    __nv_bfloat16* sKh = sc_sm + 2 * SC_TILE;
    __nv_bfloat16* sKl = sc_sm + 3 * SC_TILE;

    const int tid  = threadIdx.x;
    const int lane = tid & 31;
    const int wid  = tid >> 5;
    const int wm   = (wid >> 2) * 64;
    const int wn   = (wid & 3) * 32;
    const int m0 = blockIdx.y * 128;
    const int n0 = blockIdx.x * 128;
    const int bhx = blockIdx.z;

    const float* Qg = g_q + (size_t)bhx * SEQ * HD;
    const float* Kg = g_k + (size_t)bhx * SEQ * HD;

    // zero pad columns [72,80) of all tiles
    for (int r = tid; r < 128; r += 256) {
        *(uint2*)(sQh + r * SC_TS + 72) = make_uint2(0, 0);
        *(uint2*)(sQh + r * SC_TS + 76) = make_uint2(0, 0);
        *(uint2*)(sQl + r * SC_TS + 72) = make_uint2(0, 0);
        *(uint2*)(sQl + r * SC_TS + 76) = make_uint2(0, 0);
        *(uint2*)(sKh + r * SC_TS + 72) = make_uint2(0, 0);
        *(uint2*)(sKh + r * SC_TS + 76) = make_uint2(0, 0);
        *(uint2*)(sKl + r * SC_TS + 72) = make_uint2(0, 0);
        *(uint2*)(sKl + r * SC_TS + 76) = make_uint2(0, 0);
    }

    // stage Q and K tiles (128 x 72 fp32 each -> hi/lo bf16)
    for (int idx = tid; idx < 128 * 18; idx += 256) {
        const int row = idx / 18;
        const int c4  = (idx % 18) * 4;
        float4 qv = *(const float4*)(Qg + (size_t)(m0 + row) * HD + c4);
        float4 kv = *(const float4*)(Kg + (size_t)(n0 + row) * HD + c4);
        uint2 h, l;
        split8(h, l, qv);
        *(uint2*)(sQh + row * SC_TS + c4) = h;
        *(uint2*)(sQl + row * SC_TS + c4) = l;
        split8(h, l, kv);
        *(uint2*)(sKh + row * SC_TS + c4) = h;
        *(uint2*)(sKl + row * SC_TS + c4) = l;
    }
    __syncthreads();

    const uint32_t ah = smem_u32(sQh), al = smem_u32(sQl);
    const uint32_t bh = smem_u32(sKh), bl = smem_u32(sKl);

    float acc[4][4][4];
#pragma unroll
    for (int i = 0; i < 4; i++)
#pragma unroll
        for (int j = 0; j < 4; j++)
#pragma unroll
            for (int q = 0; q < 4; q++) acc[i][j][q] = 0.f;

    const uint32_t a_off = (wm + (lane & 15)) * (SC_TS * 2) + (lane >> 4) * 16;
    const uint32_t b_row_base = wn + (lane & 7);
    const uint32_t b_off = ((lane >> 3) & 1) * 16;

#pragma unroll
    for (int ks = 0; ks < 5; ks++) {
        uint32_t Ah[4][4], Al[4][4], Bh[4][2], Bl[4][2];
#pragma unroll
        for (int mf = 0; mf < 4; mf++) {
            const uint32_t addr = a_off + mf * 16 * (SC_TS * 2) + ks * 32;
            ldsm_x4(Ah[mf][0], Ah[mf][1], Ah[mf][2], Ah[mf][3], ah + addr);
            ldsm_x4(Al[mf][0], Al[mf][1], Al[mf][2], Al[mf][3], al + addr);
        }
#pragma unroll
        for (int nf = 0; nf < 4; nf++) {
            const uint32_t addr = (b_row_base + nf * 8) * (SC_TS * 2) + ks * 32 + b_off;
            ldsm_x2(Bh[nf][0], Bh[nf][1], bh + addr);
            ldsm_x2(Bl[nf][0], Bl[nf][1], bl + addr);
        }
#pragma unroll
        for (int mf = 0; mf < 4; mf++)
#pragma unroll
            for (int nf = 0; nf < 4; nf++) {
                mma16816(acc[mf][nf], Ah[mf][0], Ah[mf][1], Ah[mf][2], Ah[mf][3],
                         Bh[nf][0], Bh[nf][1]);
                mma16816(acc[mf][nf], Al[mf][0], Al[mf][1], Al[mf][2], Al[mf][3],
                         Bh[nf][0], Bh[nf][1]);
                mma16816(acc[mf][nf], Ah[mf][0], Ah[mf][1], Ah[mf][2], Ah[mf][3],
                         Bl[nf][0], Bl[nf][1]);
            }
    }

    float* Sg = probs + (size_t)bhx * SEQ * SEQ;
    const int r_base = m0 + wm + (lane >> 2);
    const int c_base = n0 + wn + (lane & 3) * 2;
#pragma unroll
    for (int mf = 0; mf < 4; mf++)
#pragma unroll
        for (int nf = 0; nf < 4; nf++)
#pragma unroll
            for (int half = 0; half < 2; half++) {
                const int row = r_base + mf * 16 + half * 8;
                const int col = c_base + nf * 8;
                float2 v;
                v.x = acc[mf][nf][half * 2 + 0] * SCALE_F;
                v.y = acc[mf][nf][half * 2 + 1] * SCALE_F;
                *(float2*)(Sg + (size_t)row * SEQ + col) = v;
            }
}

// ---------------------------------------------------------------------------
// Kernel 3: in-place row softmax over probs.
// ---------------------------------------------------------------------------
__global__ __launch_bounds__(256) void softmax_kernel(float* __restrict__ probs)
{
    __shared__ float red[8];
    const int tid = threadIdx.x;
    const int wid = tid >> 5, lane = tid & 31;
    float4* p = (float4*)(probs + (size_t)blockIdx.x * SEQ);

    float4 v = p[tid];
    float m = fmaxf(fmaxf(v.x, v.y), fmaxf(v.z, v.w));
#pragma unroll
    for (int o = 16; o; o >>= 1) m = fmaxf(m, __shfl_xor_sync(~0u, m, o));
    if (lane == 0) red[wid] = m;
    __syncthreads();
    m = fmaxf(fmaxf(fmaxf(red[0], red[1]), fmaxf(red[2], red[3])),
              fmaxf(fmaxf(red[4], red[5]), fmaxf(red[6], red[7])));

    v.x = __expf(v.x - m); v.y = __expf(v.y - m);
    v.z = __expf(v.z - m); v.w = __expf(v.w - m);
    float s = v.x + v.y + v.z + v.w;
#pragma unroll
    for (int o = 16; o; o >>= 1) s += __shfl_xor_sync(~0u, s, o);
    __syncthreads();
    if (lane == 0) red[wid] = s;
    __syncthreads();
    s = (red[0] + red[1] + red[2] + red[3]) +
        (red[4] + red[5] + red[6] + red[7]);
    const float inv = 1.f / s;
    v.x *= inv; v.y *= inv; v.z *= inv; v.w *= inv;
    p[tid] = v;
}

// ===========================================================================
// Kernel 4: PV GEMM on HMMA bf16x3.
//   ctx = P[1024,1024] @ V[1024,72] -> [B,N,D] layout.
//   CTA: M=128, N=96 (72 padded), K in chunks of 64.
//   P tiles [128][72-stride] (144B == 4 banks mod 32, conflict-free);
//   V staged transposed [n][k] same stride.
// ===========================================================================
#define PV_TS 72
#define PV_P_TILE (128 * PV_TS)
#define PV_V_TILE (96 * PV_TS)
#define PV_SMEM_BYTES ((2 * PV_P_TILE + 2 * PV_V_TILE) * 2)   // 64512

__global__ __launch_bounds__(256) void pv_tc_kernel(const float* __restrict__ probs)
{
    extern __shared__ __nv_bfloat16 pv_sm[];
    __nv_bfloat16* sPh = pv_sm;
    __nv_bfloat16* sPl = pv_sm + PV_P_TILE;
    __nv_bfloat16* sVh = pv_sm + 2 * PV_P_TILE;
    __nv_bfloat16* sVl = pv_sm + 2 * PV_P_TILE + PV_V_TILE;

    const int tid  = threadIdx.x;
    const int lane = tid & 31;
    const int wid  = tid >> 5;
    const int wm   = (wid >> 2) * 64;   // 0/64
    const int wn   = (wid & 3) * 24;    // 0/24/48/72
    const int m0 = blockIdx.x * 128;
    const int bhx = blockIdx.y;
    const int bb = bhx >> 4, hh = bhx & 15;

    const float* Pg = probs + (size_t)bhx * SEQ * SEQ;
    const float* Vg = g_v   + (size_t)bhx * SEQ * HD;

    // zero V pad rows [72,96) once (staging never touches them)
    for (int i = tid; i < 24 * 18; i += 256) {
        const int r = 72 + i / 18;
        const int c = (i % 18) * 4;
        *(uint2*)(sVh + r * PV_TS + c) = make_uint2(0, 0);
        *(uint2*)(sVl + r * PV_TS + c) = make_uint2(0, 0);
    }

    const uint32_t ah = smem_u32(sPh), al = smem_u32(sPl);
    const uint32_t bh = smem_u32(sVh), bl = smem_u32(sVl);

    float acc[4][3][4];
#pragma unroll
    for (int i = 0; i < 4; i++)
#pragma unroll
        for (int j = 0; j < 3; j++)
#pragma unroll
            for (int q = 0; q < 4; q++) acc[i][j][q] = 0.f;

    const uint32_t a_off = (wm + (lane & 15)) * (PV_TS * 2) + (lane >> 4) * 16;
    const uint32_t b_row_base = wn + (lane & 7);
    const uint32_t b_off = ((lane >> 3) & 1) * 16;

    for (int k0 = 0; k0 < SEQ; k0 += 64) {
        __syncthreads();
        // stage P tile 128x64 fp32 -> hi/lo
#pragma unroll
        for (int t = 0; t < 8; t++) {
            const int idx = tid + t * 256;     // 0..2047
            const int row = idx >> 4;
            const int c4  = (idx & 15) << 2;
            float4 pvv = *(const float4*)(Pg + (size_t)(m0 + row) * SEQ + k0 + c4);
            uint2 h, l;
            split8(h, l, pvv);
            *(uint2*)(sPh + row * PV_TS + c4) = h;
            *(uint2*)(sPl + row * PV_TS + c4) = l;
        }
        // stage V 64x72 fp32 transposed -> [n][k] hi/lo
        for (int idx = tid; idx < 64 * 18; idx += 256) {
            const int srow = idx / 18;         // seq index in chunk
            const int c4   = (idx % 18) * 4;   // hd base
            float4 vv = *(const float4*)(Vg + (size_t)(k0 + srow) * HD + c4);
            __nv_bfloat16 hi[4], lo[4];
            split4s(vv, hi, lo);
#pragma unroll
            for (int j = 0; j < 4; j++) {
                sVh[(c4 + j) * PV_TS + srow] = hi[j];
                sVl[(c4 + j) * PV_TS + srow] = lo[j];
            }
        }
        __syncthreads();

#pragma unroll
        for (int ks = 0; ks < 4; ks++) {
            uint32_t Ah[4][4], Al[4][4], Bh[3][2], Bl[3][2];
#pragma unroll
            for (int mf = 0; mf < 4; mf++) {
                const uint32_t addr = a_off + mf * 16 * (PV_TS * 2) + ks * 32;
                ldsm_x4(Ah[mf][0], Ah[mf][1], Ah[mf][2], Ah[mf][3], ah + addr);
                ldsm_x4(Al[mf][0], Al[mf][1], Al[mf][2], Al[mf][3], al + addr);
            }
#pragma unroll
            for (int nf = 0; nf < 3; nf++) {
                const uint32_t addr = (b_row_base + nf * 8) * (PV_TS * 2) + ks * 32 + b_off;
                ldsm_x2(Bh[nf][0], Bh[nf][1], bh + addr);
                ldsm_x2(Bl[nf][0], Bl[nf][1], bl + addr);
            }
#pragma unroll
            for (int mf = 0; mf < 4; mf++)
#pragma unroll
                for (int nf = 0; nf < 3; nf++) {
                    mma16816(acc[mf][nf], Ah[mf][0], Ah[mf][1], Ah[mf][2], Ah[mf][3],
                             Bh[nf][0], Bh[nf][1]);
                    mma16816(acc[mf][nf], Al[mf][0], Al[mf][1], Al[mf][2], Al[mf][3],
                             Bh[nf][0], Bh[nf][1]);
                    mma16816(acc[mf][nf], Ah[mf][0], Ah[mf][1], Ah[mf][2], Ah[mf][3],
                             Bl[nf][0], Bl[nf][1]);
                }
        }
    }

    // epilogue -> g_ctx [B,N,D]; skip padded cols >= 72
    const int r_base = m0 + wm + (lane >> 2);
    const int c_base = wn + (lane & 3) * 2;
#pragma unroll
    for (int mf = 0; mf < 4; mf++)
#pragma unroll
        for (int nf = 0; nf < 3; nf++) {
            const int col = c_base + nf * 8;
            if (col < HD) {
#pragma unroll
                for (int half = 0; half < 2; half++) {
                    const int row = r_base + mf * 16 + half * 8;
                    float2 v;
                    v.x = acc[mf][nf][half * 2 + 0];
                    v.y = acc[mf][nf][half * 2 + 1];
                    *(float2*)(g_ctx + ((size_t)bb * SEQ + row) * DIM
                               + hh * HD + col) = v;
                }
            }
        }
}

// ---------------------------------------------------------------------------
extern "C" void kernel_launch(void* const* d_in, const int* in_sizes, int n_in,
                              void* d_out, int out_size)
{
    const float* x  = (const float*)d_in[0];
    const float* qw = (const float*)d_in[1];
    const float* qb = (const float*)d_in[2];
    const float* kw = (const float*)d_in[3];
    const float* kb = (const float*)d_in[4];
    const float* vw = (const float*)d_in[5];
    const float* vb = (const float*)d_in[6];
    const float* ow = (const float*)d_in[7];
    const float* ob = (const float*)d_in[8];

    float* out   = (float*)d_out;            // [B,N,D]
    float* probs = out + OUT_ELEMS;          // [B,H,N,N]

    cudaFuncSetAttribute(scores_tc_kernel,
                         cudaFuncAttributeMaxDynamicSharedMemorySize,
                         SCORES_SMEM_BYTES);
    cudaFuncSetAttribute(pv_tc_kernel,
                         cudaFuncAttributeMaxDynamicSharedMemorySize,
                         PV_SMEM_BYTES);

    dim3 gq(DIM / 128, MTOT / 128, 3);       // (9, 64, 3)
    qkv_tc_kernel<<<gq, 256>>>(x, qw, qb, kw, kb, vw, vb);

    dim3 gs(SEQ / 128, SEQ / 128, BD * NH);  // (8, 8, 128)
    scores_tc_kernel<<<gs, 256, SCORES_SMEM_BYTES>>>(probs);

    softmax_kernel<<<BD * NH * SEQ, 256>>>(probs);

    dim3 gp(SEQ / 128, BD * NH);             // (8, 128)
    pv_tc_kernel<<<gp, 256, PV_SMEM_BYTES>>>(probs);

    dim3 go(DIM / 128, MTOT / 128);          // (9, 64)
    oproj_tc_kernel<<<go, 256>>>(ow, ob, out);
}

// round 7
// speedup vs baseline: 2.7233x; 1.0146x over previous
#include <cuda_runtime.h>
#include <cuda_bf16.h>
#include <cstdint>
#include <math.h>

// ---------------------------------------------------------------------------
// SiglipAttention: B=8, N=1024, D=1152, H=16, Hd=72
// Outputs (concatenated in d_out): out [B,N,D] fp32, attn_probs [B,H,N,N] fp32
// ---------------------------------------------------------------------------

#define BD   8
#define SEQ  1024
#define DIM  1152
#define NH   16
#define HD   72
#define MTOT (BD * SEQ)                 // 8192
#define QKV_ELEMS (BD * NH * SEQ * HD)  // 9437184
#define OUT_ELEMS (BD * SEQ * DIM)      // 9437184
#define SCALE_F 0.117851130197757931f   // 72^-0.5

// Scratch (allocation-free rule: __device__ globals)
__device__ float g_q[QKV_ELEMS];    // [B,H,N,Hd]
__device__ float g_k[QKV_ELEMS];    // [B,H,N,Hd]
__device__ float g_v[QKV_ELEMS];    // [B,H,N,Hd]
__device__ float g_ctx[OUT_ELEMS];  // [B,N,D]  (row layout for O-proj)

// ===========================================================================
// HMMA helpers (sm_80+ mma.sync path — tcgen05 unavailable: harness PTX
// targets sm_103 base, not sm_103a)
// ===========================================================================
__device__ __forceinline__ uint32_t smem_u32(const void* p) {
    uint32_t a;
    asm("{ .reg .u64 t; cvta.to.shared.u64 t, %1; cvt.u32.u64 %0, t; }"
        : "=r"(a) : "l"(p));
    return a;
}

__device__ __forceinline__ void ldsm_x4(uint32_t& r0, uint32_t& r1,
                                        uint32_t& r2, uint32_t& r3, uint32_t a) {
    asm volatile("ldmatrix.sync.aligned.m8n8.x4.shared.b16 {%0,%1,%2,%3}, [%4];"
                 : "=r"(r0), "=r"(r1), "=r"(r2), "=r"(r3) : "r"(a));
}
__device__ __forceinline__ void ldsm_x2(uint32_t& r0, uint32_t& r1, uint32_t a) {
    asm volatile("ldmatrix.sync.aligned.m8n8.x2.shared.b16 {%0,%1}, [%2];"
                 : "=r"(r0), "=r"(r1) : "r"(a));
}
__device__ __forceinline__ void mma16816(float* c,
                                         uint32_t a0, uint32_t a1, uint32_t a2, uint32_t a3,
                                         uint32_t b0, uint32_t b1) {
    asm volatile(
        "mma.sync.aligned.m16n8k16.row.col.f32.bf16.bf16.f32 "
        "{%0,%1,%2,%3}, {%4,%5,%6,%7}, {%8,%9}, {%0,%1,%2,%3};"
        : "+f"(c[0]), "+f"(c[1]), "+f"(c[2]), "+f"(c[3])
        : "r"(a0), "r"(a1), "r"(a2), "r"(a3), "r"(b0), "r"(b1));
}

// split fp32x4 -> hi bf16x4 + lo bf16x4 (packed as uint2 each)
__device__ __forceinline__ void split8(uint2& hi, uint2& lo, float4 v) {
    __nv_bfloat162 h01 = __floats2bfloat162_rn(v.x, v.y);
    __nv_bfloat162 h23 = __floats2bfloat162_rn(v.z, v.w);
    float rx = v.x - __bfloat162float(h01.x);
    float ry = v.y - __bfloat162float(h01.y);
    float rz = v.z - __bfloat162float(h23.x);
    float rw = v.w - __bfloat162float(h23.y);
    hi = make_uint2(*(uint32_t*)&h01, *(uint32_t*)&h23);
    __nv_bfloat162 l01 = __floats2bfloat162_rn(rx, ry);
    __nv_bfloat162 l23 = __floats2bfloat162_rn(rz, rw);
    lo = make_uint2(*(uint32_t*)&l01, *(uint32_t*)&l23);
}

// split fp32x2 -> packed bf16x2 hi + bf16x2 lo
__device__ __forceinline__ void split2(uint32_t& hi, uint32_t& lo, float x, float y) {
    __nv_bfloat162 h = __floats2bfloat162_rn(x, y);
    float rx = x - __bfloat162float(h.x);
    float ry = y - __bfloat162float(h.y);
    hi = *(uint32_t*)&h;
    __nv_bfloat162 l = __floats2bfloat162_rn(rx, ry);
    lo = *(uint32_t*)&l;
}

// split fp32x4 -> 4 separate hi bf16 + 4 lo bf16 (for transposed scatter)
__device__ __forceinline__ void split4s(float4 v,
                                        __nv_bfloat16* hi, __nv_bfloat16* lo) {
    hi[0] = __float2bfloat16_rn(v.x);
    hi[1] = __float2bfloat16_rn(v.y);
    hi[2] = __float2bfloat16_rn(v.z);
    hi[3] = __float2bfloat16_rn(v.w);
    lo[0] = __float2bfloat16_rn(v.x - __bfloat162float(hi[0]));
    lo[1] = __float2bfloat16_rn(v.y - __bfloat162float(hi[1]));
    lo[2] = __float2bfloat16_rn(v.z - __bfloat162float(hi[2]));
    lo[3] = __float2bfloat16_rn(v.w - __bfloat162float(hi[3]));
}

// ===========================================================================
// Common bf16x3 HMMA GEMM device core:  y[128,128]tile = A[M,K] @ W[N,K]^T
// K consumed in chunks of 32.  MODE 0: head-scatter epilogue (qkv);
// MODE 1: plain [M,DIM] epilogue (o-proj).
// smem tiles [128][40] bf16 (80B stride -> conflict-free ldmatrix).
// ===========================================================================
#define TSTR 40   // bf16 elements per smem row (80 bytes)

template <int MODE>
__device__ __forceinline__ void tc_gemm_tile(
    const float* __restrict__ A, const float* __restrict__ W,
    const float* __restrict__ bias, float* __restrict__ dst,
    int m0, int n0)
{
    __shared__ __nv_bfloat16 sAh[128 * TSTR], sAl[128 * TSTR];
    __shared__ __nv_bfloat16 sBh[128 * TSTR], sBl[128 * TSTR];

    const int tid  = threadIdx.x;
    const int lane = tid & 31;
    const int wid  = tid >> 5;
    const int wm   = (wid >> 2) * 64;   // warp m-offset (0/64)
    const int wn   = (wid & 3) * 32;    // warp n-offset (0/32/64/96)

    const uint32_t ah = smem_u32(sAh), al = smem_u32(sAl);
    const uint32_t bh = smem_u32(sBh), bl = smem_u32(sBl);

    float acc[4][4][4];
#pragma unroll
    for (int i = 0; i < 4; i++)
#pragma unroll
        for (int j = 0; j < 4; j++)
#pragma unroll
            for (int q = 0; q < 4; q++) acc[i][j][q] = 0.f;

    const uint32_t a_row = wm + (lane & 15);
    const uint32_t a_off = a_row * (TSTR * 2) + (lane >> 4) * 16;
    const uint32_t b_row_base = wn + (lane & 7);
    const uint32_t b_off = ((lane >> 3) & 1) * 16;

    for (int k0 = 0; k0 < DIM; k0 += 32) {
        __syncthreads();
#pragma unroll
        for (int t = 0; t < 4; t++) {
            const int idx = tid + t * 256;         // 0..1023
            const int row = idx >> 3;
            const int c4  = (idx & 7) << 2;
            float4 av = *(const float4*)(A + (size_t)(m0 + row) * DIM + k0 + c4);
            float4 wv = *(const float4*)(W + (size_t)(n0 + row) * DIM + k0 + c4);
            uint2 h, l;
            split8(h, l, av);
            *(uint2*)(sAh + row * TSTR + c4) = h;
            *(uint2*)(sAl + row * TSTR + c4) = l;
            split8(h, l, wv);
            *(uint2*)(sBh + row * TSTR + c4) = h;
            *(uint2*)(sBl + row * TSTR + c4) = l;
        }
        __syncthreads();

#pragma unroll
        for (int ks = 0; ks < 2; ks++) {
            uint32_t Ah[4][4], Al[4][4], Bh[4][2], Bl[4][2];
#pragma unroll
            for (int mf = 0; mf < 4; mf++) {
                const uint32_t addr = a_off + mf * 16 * (TSTR * 2) + ks * 32;
                ldsm_x4(Ah[mf][0], Ah[mf][1], Ah[mf][2], Ah[mf][3], ah + addr);
                ldsm_x4(Al[mf][0], Al[mf][1], Al[mf][2], Al[mf][3], al + addr);
            }
#pragma unroll
            for (int nf = 0; nf < 4; nf++) {
                const uint32_t addr = (b_row_base + nf * 8) * (TSTR * 2) + ks * 32 + b_off;
                ldsm_x2(Bh[nf][0], Bh[nf][1], bh + addr);
                ldsm_x2(Bl[nf][0], Bl[nf][1], bl + addr);
            }
#pragma unroll
            for (int mf = 0; mf < 4; mf++)
#pragma unroll
                for (int nf = 0; nf < 4; nf++) {
                    mma16816(acc[mf][nf], Ah[mf][0], Ah[mf][1], Ah[mf][2], Ah[mf][3],
                             Bh[nf][0], Bh[nf][1]);
                    mma16816(acc[mf][nf], Al[mf][0], Al[mf][1], Al[mf][2], Al[mf][3],
                             Bh[nf][0], Bh[nf][1]);
                    mma16816(acc[mf][nf], Ah[mf][0], Ah[mf][1], Ah[mf][2], Ah[mf][3],
                             Bl[nf][0], Bl[nf][1]);
                }
        }
    }

    const int r_base = m0 + wm + (lane >> 2);
    const int c_base = n0 + wn + (lane & 3) * 2;
#pragma unroll
    for (int mf = 0; mf < 4; mf++) {
#pragma unroll
        for (int nf = 0; nf < 4; nf++) {
            const int col = c_base + nf * 8;
            const float bx = bias[col], by = bias[col + 1];
#pragma unroll
            for (int half = 0; half < 2; half++) {
                const int row = r_base + mf * 16 + half * 8;
                float2 v;
                v.x = acc[mf][nf][half * 2 + 0] + bx;
                v.y = acc[mf][nf][half * 2 + 1] + by;
                if (MODE == 0) {
                    const int bb = row >> 10, n = row & 1023;
                    const int h = col / HD, hd = col % HD;
                    *(float2*)(dst + ((size_t)(bb * NH + h) * SEQ + n) * HD + hd) = v;
                } else {
                    *(float2*)(dst + (size_t)row * DIM + col) = v;
                }
            }
        }
    }
}

// Kernel 1: QKV projection (z picks proj, head-scatter epilogue)
__global__ __launch_bounds__(256) void qkv_tc_kernel(
    const float* __restrict__ x,
    const float* __restrict__ qw, const float* __restrict__ qb,
    const float* __restrict__ kw, const float* __restrict__ kb,
    const float* __restrict__ vw, const float* __restrict__ vb)
{
    const int proj = blockIdx.z;
    const float* w    = (proj == 0) ? qw : (proj == 1) ? kw : vw;
    const float* bias = (proj == 0) ? qb : (proj == 1) ? kb : vb;
    float* dst        = (proj == 0) ? g_q : (proj == 1) ? g_k : g_v;
    tc_gemm_tile<0>(x, w, bias, dst, blockIdx.y * 128, blockIdx.x * 128);
}

// Kernel 5: O projection (plain epilogue, A = ctx in [M,DIM])
__global__ __launch_bounds__(256) void oproj_tc_kernel(
    const float* __restrict__ ow, const float* __restrict__ ob,
    float* __restrict__ out)
{
    tc_gemm_tile<1>(g_ctx, ow, ob, out, blockIdx.y * 128, blockIdx.x * 128);
}

// ===========================================================================
// Kernel 2: FUSED scores + softmax.
//   Per CTA: 16 q-rows x all 1024 keys of one (b,h).
//   S tile fp32 in smem [16][1026]; Q lives in A-frag registers (hi/lo bf16,
//   loaded once); K staged per 128-key tile (stride 88, conflict-free).
//   After the k-loop: in-CTA row softmax, single coalesced probs write.
// ===========================================================================
#define FS_KSTR 88
#define FS_SSTR 1026
#define FS_S_BYTES (16 * FS_SSTR * 4)            // 65664
#define FS_K_BYTES (128 * FS_KSTR * 2)           // 22528 per tile
#define FS_SMEM (FS_S_BYTES + 2 * FS_K_BYTES)    // 110720

__global__ __launch_bounds__(256, 2) void fused_scores_softmax_kernel(
    float* __restrict__ probs)
{
    extern __shared__ char fsm[];
    float* S = (float*)fsm;
    __nv_bfloat16* Kh = (__nv_bfloat16*)(fsm + FS_S_BYTES);
    __nv_bfloat16* Kl = Kh + 128 * FS_KSTR;

    const int tid  = threadIdx.x;
    const int lane = tid & 31;
    const int w    = tid >> 5;
    const int q0   = blockIdx.x * 16;
    const int bhx  = blockIdx.y;

    const float* Qg = g_q + (size_t)bhx * SEQ * HD + (size_t)q0 * HD;
    const float* Kg = g_k + (size_t)bhx * SEQ * HD;

    // ---- load Q A-fragments directly to registers (hi/lo bf16 split) ----
    // m16n8k16 A layout: reg j for lane l covers (row = (l>>2) + (j&1)*8,
    // cols = ks*16 + (l&3)*2 + (j>>1)*8 + {0,1})
    uint32_t Qh[5][4], Ql[5][4];
    {
        const int r  = lane >> 2;
        const int c0 = (lane & 3) * 2;
#pragma unroll
        for (int ks = 0; ks < 5; ks++)
#pragma unroll
            for (int j = 0; j < 4; j++) {
                const int rr = r + (j & 1) * 8;
                const int cc = ks * 16 + c0 + (j >> 1) * 8;
                float x = 0.f, y = 0.f;
                if (cc < 72) {
                    const float2 v = *(const float2*)(Qg + (size_t)rr * HD + cc);
                    x = v.x; y = v.y;
                }
                split2(Qh[ks][j], Ql[ks][j], x, y);
            }
    }

    // zero K pad columns [72,80) once (staging never writes them)
    for (int r = tid; r < 128; r += 256) {
        *(uint2*)(Kh + r * FS_KSTR + 72) = make_uint2(0, 0);
        *(uint2*)(Kh + r * FS_KSTR + 76) = make_uint2(0, 0);
        *(uint2*)(Kl + r * FS_KSTR + 72) = make_uint2(0, 0);
        *(uint2*)(Kl + r * FS_KSTR + 76) = make_uint2(0, 0);
    }

    const uint32_t kh = smem_u32(Kh), kl = smem_u32(Kl);
    const uint32_t b_row = w * 16 + (lane & 7);
    const uint32_t b_off = ((lane >> 3) & 1) * 16;

    for (int kb = 0; kb < 8; kb++) {
        __syncthreads();   // K buffer free (prev compute done)
        // stage K tile 128x72 fp32 -> hi/lo bf16
        for (int idx = tid; idx < 128 * 18; idx += 256) {
            const int row = idx / 18;
            const int c4  = (idx % 18) * 4;
            float4 kv = *(const float4*)(Kg + (size_t)(kb * 128 + row) * HD + c4);
            uint2 h, l;
            split8(h, l, kv);
            *(uint2*)(Kh + row * FS_KSTR + c4) = h;
            *(uint2*)(Kl + row * FS_KSTR + c4) = l;
        }
        __syncthreads();

        float acc[2][4];
#pragma unroll
        for (int nf = 0; nf < 2; nf++)
#pragma unroll
            for (int q = 0; q < 4; q++) acc[nf][q] = 0.f;

#pragma unroll
        for (int ks = 0; ks < 5; ks++) {
            uint32_t Bh[2][2], Bl[2][2];
#pragma unroll
            for (int nf = 0; nf < 2; nf++) {
                const uint32_t addr = (b_row + nf * 8) * (FS_KSTR * 2) + ks * 32 + b_off;
                ldsm_x2(Bh[nf][0], Bh[nf][1], kh + addr);
                ldsm_x2(Bl[nf][0], Bl[nf][1], kl + addr);
            }
#pragma unroll
            for (int nf = 0; nf < 2; nf++) {
                mma16816(acc[nf], Qh[ks][0], Qh[ks][1], Qh[ks][2], Qh[ks][3],
                         Bh[nf][0], Bh[nf][1]);
                mma16816(acc[nf], Ql[ks][0], Ql[ks][1], Ql[ks][2], Ql[ks][3],
                         Bh[nf][0], Bh[nf][1]);
                mma16816(acc[nf], Qh[ks][0], Qh[ks][1], Qh[ks][2], Qh[ks][3],
                         Bl[nf][0], Bl[nf][1]);
            }
        }

        // write scaled scores into S smem
        const int r = lane >> 2;
        const int c = (lane & 3) * 2;
#pragma unroll
        for (int nf = 0; nf < 2; nf++)
#pragma unroll
            for (int half = 0; half < 2; half++) {
                const int row = r + half * 8;
                const int col = kb * 128 + w * 16 + nf * 8 + c;
                float2 v;
                v.x = acc[nf][half * 2 + 0] * SCALE_F;
                v.y = acc[nf][half * 2 + 1] * SCALE_F;
                *(float2*)(S + row * FS_SSTR + col) = v;
            }
    }
    __syncthreads();

    // ---- softmax: warp w handles rows 2w, 2w+1; write probs once ----
#pragma unroll
    for (int rr = 0; rr < 2; rr++) {
        const int row = w * 2 + rr;
        float2 v[16];
#pragma unroll
        for (int i = 0; i < 16; i++)
            v[i] = *(const float2*)(S + row * FS_SSTR + lane * 2 + i * 64);
        float m = -1e30f;
#pragma unroll
        for (int i = 0; i < 16; i++) m = fmaxf(m, fmaxf(v[i].x, v[i].y));
#pragma unroll
        for (int o = 16; o; o >>= 1) m = fmaxf(m, __shfl_xor_sync(~0u, m, o));
        float s = 0.f;
#pragma unroll
        for (int i = 0; i < 16; i++) {
            v[i].x = __expf(v[i].x - m);
            v[i].y = __expf(v[i].y - m);
            s += v[i].x + v[i].y;
        }
#pragma unroll
        for (int o = 16; o; o >>= 1) s += __shfl_xor_sync(~0u, s, o);
        const float inv = 1.f / s;
        float* pg = probs + ((size_t)bhx * SEQ + q0 + row) * SEQ;
#pragma unroll
        for (int i = 0; i < 16; i++) {
            float2 o2;
            o2.x = v[i].x * inv;
            o2.y = v[i].y * inv;
            *(float2*)(pg + lane * 2 + i * 64) = o2;
        }
    }
}

// ===========================================================================
// Kernel 4: PV GEMM on HMMA bf16x3.
//   ctx = P[1024,1024] @ V[1024,72] -> [B,N,D] layout.
//   CTA: M=128, N=96 (72 padded), K in chunks of 64.
// ===========================================================================
#define PV_TS 72
#define PV_P_TILE (128 * PV_TS)
#define PV_V_TILE (96 * PV_TS)
#define PV_SMEM_BYTES ((2 * PV_P_TILE + 2 * PV_V_TILE) * 2)   // 64512

__global__ __launch_bounds__(256) void pv_tc_kernel(const float* __restrict__ probs)
{
    extern __shared__ __nv_bfloat16 pv_sm[];
    __nv_bfloat16* sPh = pv_sm;
    __nv_bfloat16* sPl = pv_sm + PV_P_TILE;
    __nv_bfloat16* sVh = pv_sm + 2 * PV_P_TILE;
    __nv_bfloat16* sVl = pv_sm + 2 * PV_P_TILE + PV_V_TILE;

    const int tid  = threadIdx.x;
    const int lane = tid & 31;
    const int wid  = tid >> 5;
    const int wm   = (wid >> 2) * 64;   // 0/64
    const int wn   = (wid & 3) * 24;    // 0/24/48/72
    const int m0 = blockIdx.x * 128;
    const int bhx = blockIdx.y;
    const int bb = bhx >> 4, hh = bhx & 15;

    const float* Pg = probs + (size_t)bhx * SEQ * SEQ;
    const float* Vg = g_v   + (size_t)bhx * SEQ * HD;

    // zero V pad rows [72,96)
    for (int i = tid; i < 24 * 18; i += 256) {
        const int r = 72 + i / 18;
        const int c = (i % 18) * 4;
        *(uint2*)(sVh + r * PV_TS + c) = make_uint2(0, 0);
        *(uint2*)(sVl + r * PV_TS + c) = make_uint2(0, 0);
    }

    const uint32_t ah = smem_u32(sPh), al = smem_u32(sPl);
    const uint32_t bh = smem_u32(sVh), bl = smem_u32(sVl);

    float acc[4][3][4];
#pragma unroll
    for (int i = 0; i < 4; i++)
#pragma unroll
        for (int j = 0; j < 3; j++)
#pragma unroll
            for (int q = 0; q < 4; q++) acc[i][j][q] = 0.f;

    const uint32_t a_off = (wm + (lane & 15)) * (PV_TS * 2) + (lane >> 4) * 16;
    const uint32_t b_row_base = wn + (lane & 7);
    const uint32_t b_off = ((lane >> 3) & 1) * 16;

    for (int k0 = 0; k0 < SEQ; k0 += 64) {
        __syncthreads();
#pragma unroll
        for (int t = 0; t < 8; t++) {
            const int idx = tid + t * 256;     // 0..2047
            const int row = idx >> 4;
            const int c4  = (idx & 15) << 2;
            float4 pvv = *(const float4*)(Pg + (size_t)(m0 + row) * SEQ + k0 + c4);
            uint2 h, l;
            split8(h, l, pvv);
            *(uint2*)(sPh + row * PV_TS + c4) = h;
            *(uint2*)(sPl + row * PV_TS + c4) = l;
        }
        for (int idx = tid; idx < 64 * 18; idx += 256) {
            const int srow = idx / 18;
            const int c4   = (idx % 18) * 4;
            float4 vv = *(const float4*)(Vg + (size_t)(k0 + srow) * HD + c4);
            __nv_bfloat16 hi[4], lo[4];
            split4s(vv, hi, lo);
#pragma unroll
            for (int j = 0; j < 4; j++) {
                sVh[(c4 + j) * PV_TS + srow] = hi[j];
                sVl[(c4 + j) * PV_TS + srow] = lo[j];
            }
        }
        __syncthreads();

#pragma unroll
        for (int ks = 0; ks < 4; ks++) {
            uint32_t Ah[4][4], Al[4][4], Bh[3][2], Bl[3][2];
#pragma unroll
            for (int mf = 0; mf < 4; mf++) {
                const uint32_t addr = a_off + mf * 16 * (PV_TS * 2) + ks * 32;
                ldsm_x4(Ah[mf][0], Ah[mf][1], Ah[mf][2], Ah[mf][3], ah + addr);
                ldsm_x4(Al[mf][0], Al[mf][1], Al[mf][2], Al[mf][3], al + addr);
            }
#pragma unroll
            for (int nf = 0; nf < 3; nf++) {
                const uint32_t addr = (b_row_base + nf * 8) * (PV_TS * 2) + ks * 32 + b_off;
                ldsm_x2(Bh[nf][0], Bh[nf][1], bh + addr);
                ldsm_x2(Bl[nf][0], Bl[nf][1], bl + addr);
            }
#pragma unroll
            for (int mf = 0; mf < 4; mf++)
#pragma unroll
                for (int nf = 0; nf < 3; nf++) {
                    mma16816(acc[mf][nf], Ah[mf][0], Ah[mf][1], Ah[mf][2], Ah[mf][3],
                             Bh[nf][0], Bh[nf][1]);
                    mma16816(acc[mf][nf], Al[mf][0], Al[mf][1], Al[mf][2], Al[mf][3],
                             Bh[nf][0], Bh[nf][1]);
                    mma16816(acc[mf][nf], Ah[mf][0], Ah[mf][1], Ah[mf][2], Ah[mf][3],
                             Bl[nf][0], Bl[nf][1]);
                }
        }
    }

    const int r_base = m0 + wm + (lane >> 2);
    const int c_base = wn + (lane & 3) * 2;
#pragma unroll
    for (int mf = 0; mf < 4; mf++)
#pragma unroll
        for (int nf = 0; nf < 3; nf++) {
            const int col = c_base + nf * 8;
            if (col < HD) {
#pragma unroll
                for (int half = 0; half < 2; half++) {
                    const int row = r_base + mf * 16 + half * 8;
                    float2 v;
                    v.x = acc[mf][nf][half * 2 + 0];
                    v.y = acc[mf][nf][half * 2 + 1];
                    *(float2*)(g_ctx + ((size_t)bb * SEQ + row) * DIM
                               + hh * HD + col) = v;
                }
            }
        }
}

// ---------------------------------------------------------------------------
extern "C" void kernel_launch(void* const* d_in, const int* in_sizes, int n_in,
                              void* d_out, int out_size)
{
    const float* x  = (const float*)d_in[0];
    const float* qw = (const float*)d_in[1];
    const float* qb = (const float*)d_in[2];
    const float* kw = (const float*)d_in[3];
    const float* kb = (const float*)d_in[4];
    const float* vw = (const float*)d_in[5];
    const float* vb = (const float*)d_in[6];
    const float* ow = (const float*)d_in[7];
    const float* ob = (const float*)d_in[8];

    float* out   = (float*)d_out;            // [B,N,D]
    float* probs = out + OUT_ELEMS;          // [B,H,N,N]

    cudaFuncSetAttribute(fused_scores_softmax_kernel,
                         cudaFuncAttributeMaxDynamicSharedMemorySize,
                         FS_SMEM);
    cudaFuncSetAttribute(pv_tc_kernel,
                         cudaFuncAttributeMaxDynamicSharedMemorySize,
                         PV_SMEM_BYTES);

    dim3 gq(DIM / 128, MTOT / 128, 3);       // (9, 64, 3)
    qkv_tc_kernel<<<gq, 256>>>(x, qw, qb, kw, kb, vw, vb);

    dim3 gs(SEQ / 16, BD * NH);              // (64, 128)
    fused_scores_softmax_kernel<<<gs, 256, FS_SMEM>>>(probs);

    dim3 gp(SEQ / 128, BD * NH);             // (8, 128)
    pv_tc_kernel<<<gp, 256, PV_SMEM_BYTES>>>(probs);

    dim3 go(DIM / 128, MTOT / 128);          // (9, 64)
    oproj_tc_kernel<<<go, 256>>>(ow, ob, out);
}